// round 10
// baseline (speedup 1.0000x reference)
#include <cuda_runtime.h>
#include <cuda_bf16.h>
#include <cuda_fp16.h>
#include <math.h>
#include <stdint.h>

#define NN   50000
#define EE   1600000
#define CIN  32
#define HID  128
#define LAT  64
#define HID4 (HID/4)
#define CIN4 (CIN/4)

// ---------------- scratch (device globals; no allocations allowed) ----------
__device__ int      g_ideg[NN];
__device__ int      g_cnt[NN];
__device__ int      g_rowptr[NN + 1];
__device__ __align__(16) uint32_t g_coln[EE];            // {src:16 | half(nrm):16}
__device__ __align__(16) float g_dis[NN];
__device__ __align__(16) __nv_bfloat16 g_xh[NN * CIN];   // bf16 x
__device__ __align__(16) float g_aggx[NN * CIN];
__device__ __align__(16) float g_bufA[NN * HID];         // h1 fp32
__device__ __align__(16) __nv_bfloat16 g_tB[NN * HID];   // t2 bf16
__device__ __align__(16) float g_gsum[HID];
__device__ __align__(16) float g_dvec[HID];

// ---------------- helpers ---------------------------------------------------
__device__ __forceinline__ void fma4(float4& acc, float s, const float4& v) {
    acc.x = fmaf(s, v.x, acc.x);
    acc.y = fmaf(s, v.y, acc.y);
    acc.z = fmaf(s, v.z, acc.z);
    acc.w = fmaf(s, v.w, acc.w);
}
__device__ __forceinline__ uint32_t bf2_bits(__nv_bfloat162 v) {
    return *reinterpret_cast<uint32_t*>(&v);
}
__device__ __forceinline__ void fma_bf(float4& acc, float n, uint2 u) {
    __nv_bfloat162 lo = *reinterpret_cast<__nv_bfloat162*>(&u.x);
    __nv_bfloat162 hi = *reinterpret_cast<__nv_bfloat162*>(&u.y);
    float2 f0 = __bfloat1622float2(lo);
    float2 f1 = __bfloat1622float2(hi);
    acc.x = fmaf(n, f0.x, acc.x); acc.y = fmaf(n, f0.y, acc.y);
    acc.z = fmaf(n, f1.x, acc.z); acc.w = fmaf(n, f1.y, acc.w);
}
__device__ __forceinline__ void red_add_f4(float4* p, float4 v) {
    asm volatile("red.global.add.v4.f32 [%0], {%1,%2,%3,%4};"
                 :: "l"(p), "f"(v.x), "f"(v.y), "f"(v.z), "f"(v.w)
                 : "memory");
}
__device__ __forceinline__ uint32_t pack_sn(int s, float nrm) {
    return (uint32_t)s | ((uint32_t)__half_as_ushort(__float2half_rn(nrm)) << 16);
}
__device__ __forceinline__ int up_src(uint32_t c) { return (int)(c & 0xffffu); }
__device__ __forceinline__ float up_nrm(uint32_t c) {
    return __half2float(__ushort_as_half((unsigned short)(c >> 16)));
}
// packed f32x2 math (base-Blackwell; emitted only via hand PTX)
__device__ __forceinline__ unsigned long long bcast2(float a) {
    unsigned long long r;
    asm("mov.b64 %0, {%1, %1};" : "=l"(r) : "f"(a));
    return r;
}
__device__ __forceinline__ void fmaX2(unsigned long long& acc,
                                      unsigned long long a, unsigned long long w) {
    asm("fma.rn.f32x2 %0, %1, %2, %0;" : "+l"(acc) : "l"(a), "l"(w));
}
__device__ __forceinline__ float2 unpk2(unsigned long long p) {
    float lo, hi;
    asm("mov.b64 {%0, %1}, %2;" : "=f"(lo), "=f"(hi) : "l"(p));
    return make_float2(lo, hi);
}

// ---------------- init ------------------------------------------------------
__global__ void k_init(const float* __restrict__ x) {
    int i = blockIdx.x * 256 + threadIdx.x;
    if (i < NN)  g_ideg[i] = 0;
    if (i < HID) g_gsum[i] = 0.0f;
    if (i < NN * CIN / 2) {
        float2 v = ((const float2*)x)[i];
        ((__nv_bfloat162*)g_xh)[i] = __float22bfloat162_rn(v);
    }
}

// ---------------- degree ----------------------------------------------------
__global__ void k_deg(const int* __restrict__ dst) {
    int e0 = (blockIdx.x * 256 + threadIdx.x) * 4;
    if (e0 >= EE) return;
    int4 d4 = *(const int4*)(dst + e0);
    atomicAdd(&g_ideg[d4.x], 1);
    atomicAdd(&g_ideg[d4.y], 1);
    atomicAdd(&g_ideg[d4.z], 1);
    atomicAdd(&g_ideg[d4.w], 1);
}

// ---------------- single-block scan -----------------------------------------
__global__ void __launch_bounds__(1024) k_scan() {
    const int CH = 49;
    int tid = threadIdx.x;
    int base = tid * CH;
    int local = 0;
#pragma unroll
    for (int j = 0; j < CH; j++) {
        int i = base + j;
        if (i < NN) local += g_ideg[i];
    }
    __shared__ int wsum[32];
    int lane = tid & 31, wid = tid >> 5;
    int inc = local;
#pragma unroll
    for (int off = 1; off < 32; off <<= 1) {
        int t = __shfl_up_sync(0xffffffffu, inc, off);
        if (lane >= off) inc += t;
    }
    if (lane == 31) wsum[wid] = inc;
    __syncthreads();
    if (wid == 0) {
        int v = wsum[lane];
#pragma unroll
        for (int off = 1; off < 32; off <<= 1) {
            int t = __shfl_up_sync(0xffffffffu, v, off);
            if (lane >= off) v += t;
        }
        wsum[lane] = v;
    }
    __syncthreads();
    int run = inc - local + (wid > 0 ? wsum[wid - 1] : 0);
#pragma unroll
    for (int j = 0; j < CH; j++) {
        int i = base + j;
        if (i < NN) {
            int d = g_ideg[i];
            g_rowptr[i] = run;
            g_cnt[i]    = run;
            g_dis[i] = rsqrtf((float)(d + 1));
            run += d;
        }
    }
    if (tid == 1023) g_rowptr[NN] = run;
}

// ---------------- CSR fill: packed 4B {src, half(nrm)} ----------------------
__global__ void k_fill(const int* __restrict__ ei) {
    int e0 = (blockIdx.x * 256 + threadIdx.x) * 4;
    if (e0 >= EE) return;
    int4 s4 = *(const int4*)(ei + e0);
    int4 d4 = *(const int4*)(ei + EE + e0);
    float a0 = __ldg(&g_dis[s4.x]) * __ldg(&g_dis[d4.x]);
    float a1 = __ldg(&g_dis[s4.y]) * __ldg(&g_dis[d4.y]);
    float a2 = __ldg(&g_dis[s4.z]) * __ldg(&g_dis[d4.z]);
    float a3 = __ldg(&g_dis[s4.w]) * __ldg(&g_dis[d4.w]);
    int p0 = atomicAdd(&g_cnt[d4.x], 1);
    int p1 = atomicAdd(&g_cnt[d4.y], 1);
    int p2 = atomicAdd(&g_cnt[d4.z], 1);
    int p3 = atomicAdd(&g_cnt[d4.w], 1);
    g_coln[p0] = pack_sn(s4.x, a0);
    g_coln[p1] = pack_sn(s4.y, a1);
    g_coln[p2] = pack_sn(s4.z, a2);
    g_coln[p3] = pack_sn(s4.w, a3);
}

// ---------------- layer-1 gather --------------------------------------------
__global__ void __launch_bounds__(256) k_gather1() {
    int w = (blockIdx.x * 256 + threadIdx.x) >> 5;
    int lane = threadIdx.x & 31;
    if (w >= NN) return;
    float di = g_dis[w];
    int e   = g_rowptr[w];
    int end = g_rowptr[w + 1];
    float acc = __bfloat162float(g_xh[w * CIN + lane]) * di * di;
    int e4 = e + ((end - e) & ~3);
    for (; e < e4; e += 4) {
        uint32_t c0 = __ldg(&g_coln[e]);
        uint32_t c1 = __ldg(&g_coln[e + 1]);
        uint32_t c2 = __ldg(&g_coln[e + 2]);
        uint32_t c3 = __ldg(&g_coln[e + 3]);
        float v0 = __bfloat162float(g_xh[up_src(c0) * CIN + lane]);
        float v1 = __bfloat162float(g_xh[up_src(c1) * CIN + lane]);
        float v2 = __bfloat162float(g_xh[up_src(c2) * CIN + lane]);
        float v3 = __bfloat162float(g_xh[up_src(c3) * CIN + lane]);
        acc = fmaf(v0, up_nrm(c0), acc);
        acc = fmaf(v1, up_nrm(c1), acc);
        acc = fmaf(v2, up_nrm(c2), acc);
        acc = fmaf(v3, up_nrm(c3), acc);
    }
    for (; e < end; e++) {
        uint32_t c = __ldg(&g_coln[e]);
        acc = fmaf(__bfloat162float(g_xh[up_src(c) * CIN + lane]), up_nrm(c), acc);
    }
    g_aggx[w * CIN + lane] = acc;
}

// ---------------- layer 1: h1 = relu(aggx @ W1 + b1) -> bufA ----------------
__global__ void __launch_bounds__(256) k_layer1(const float* __restrict__ W1,
                                                const float* __restrict__ b1) {
    __shared__ float sW[CIN * HID];
    __shared__ float sv[8 * CIN];
    int tid = threadIdx.x;
    int row0 = blockIdx.x * 8;
    for (int i = tid; i < CIN * HID; i += 256) sW[i] = W1[i];
    sv[tid] = g_aggx[row0 * CIN + tid];
    __syncthreads();
    int r = tid >> 5, cg = tid & 31;
    float4 acc = ((const float4*)b1)[cg];
    const float4* sW4 = (const float4*)sW;
#pragma unroll
    for (int k = 0; k < CIN; k++) {
        float a = sv[r * CIN + k];
        fma4(acc, a, sW4[k * HID4 + cg]);
    }
    acc.x = fmaxf(acc.x, 0.f); acc.y = fmaxf(acc.y, 0.f);
    acc.z = fmaxf(acc.z, 0.f); acc.w = fmaxf(acc.w, 0.f);
    ((float4*)g_bufA)[(row0 + r) * HID4 + cg] = acc;
}

// ---------------- GEMM2: tB(bf16) = bufA @ W2, packed f32x2 FMA -------------
__global__ void __launch_bounds__(256) k_gemm2(const float* __restrict__ W2) {
    int tid = threadIdx.x;
    int cg = tid & 31, rl = tid >> 5;
    int rbase = blockIdx.x * 32 + rl;
    int r0 = rbase, r1 = rbase + 8, r2 = rbase + 16, r3 = rbase + 24;
    bool v0 = r0 < NN, v1 = r1 < NN, v2 = r2 < NN, v3 = r3 < NN;
    const ulonglong2* W8 = (const ulonglong2*)W2;   // row k: 32 x ulonglong2
    const float4* A4 = (const float4*)g_bufA;
    float4 zf = make_float4(0.f, 0.f, 0.f, 0.f);
    unsigned long long aL0 = 0, aH0 = 0, aL1 = 0, aH1 = 0;
    unsigned long long aL2 = 0, aH2 = 0, aL3 = 0, aH3 = 0;
#pragma unroll 4
    for (int k4 = 0; k4 < HID4; k4++) {
        float4 x0 = v0 ? __ldg(&A4[r0 * HID4 + k4]) : zf;
        float4 x1 = v1 ? __ldg(&A4[r1 * HID4 + k4]) : zf;
        float4 x2 = v2 ? __ldg(&A4[r2 * HID4 + k4]) : zf;
        float4 x3 = v3 ? __ldg(&A4[r3 * HID4 + k4]) : zf;
        ulonglong2 w0 = __ldg(&W8[(k4 * 4 + 0) * 32 + cg]);
        ulonglong2 w1 = __ldg(&W8[(k4 * 4 + 1) * 32 + cg]);
        ulonglong2 w2 = __ldg(&W8[(k4 * 4 + 2) * 32 + cg]);
        ulonglong2 w3 = __ldg(&W8[(k4 * 4 + 3) * 32 + cg]);
        unsigned long long b;
        b = bcast2(x0.x); fmaX2(aL0, b, w0.x); fmaX2(aH0, b, w0.y);
        b = bcast2(x0.y); fmaX2(aL0, b, w1.x); fmaX2(aH0, b, w1.y);
        b = bcast2(x0.z); fmaX2(aL0, b, w2.x); fmaX2(aH0, b, w2.y);
        b = bcast2(x0.w); fmaX2(aL0, b, w3.x); fmaX2(aH0, b, w3.y);
        b = bcast2(x1.x); fmaX2(aL1, b, w0.x); fmaX2(aH1, b, w0.y);
        b = bcast2(x1.y); fmaX2(aL1, b, w1.x); fmaX2(aH1, b, w1.y);
        b = bcast2(x1.z); fmaX2(aL1, b, w2.x); fmaX2(aH1, b, w2.y);
        b = bcast2(x1.w); fmaX2(aL1, b, w3.x); fmaX2(aH1, b, w3.y);
        b = bcast2(x2.x); fmaX2(aL2, b, w0.x); fmaX2(aH2, b, w0.y);
        b = bcast2(x2.y); fmaX2(aL2, b, w1.x); fmaX2(aH2, b, w1.y);
        b = bcast2(x2.z); fmaX2(aL2, b, w2.x); fmaX2(aH2, b, w2.y);
        b = bcast2(x2.w); fmaX2(aL2, b, w3.x); fmaX2(aH2, b, w3.y);
        b = bcast2(x3.x); fmaX2(aL3, b, w0.x); fmaX2(aH3, b, w0.y);
        b = bcast2(x3.y); fmaX2(aL3, b, w1.x); fmaX2(aH3, b, w1.y);
        b = bcast2(x3.z); fmaX2(aL3, b, w2.x); fmaX2(aH3, b, w2.y);
        b = bcast2(x3.w); fmaX2(aL3, b, w3.x); fmaX2(aH3, b, w3.y);
    }
    uint2* O = (uint2*)g_tB;
    uint2 o;
    float2 p, q;
    if (v0) {
        p = unpk2(aL0); q = unpk2(aH0);
        o.x = bf2_bits(__float22bfloat162_rn(p));
        o.y = bf2_bits(__float22bfloat162_rn(q));
        O[r0 * 32 + cg] = o;
    }
    if (v1) {
        p = unpk2(aL1); q = unpk2(aH1);
        o.x = bf2_bits(__float22bfloat162_rn(p));
        o.y = bf2_bits(__float22bfloat162_rn(q));
        O[r1 * 32 + cg] = o;
    }
    if (v2) {
        p = unpk2(aL2); q = unpk2(aH2);
        o.x = bf2_bits(__float22bfloat162_rn(p));
        o.y = bf2_bits(__float22bfloat162_rn(q));
        O[r2 * 32 + cg] = o;
    }
    if (v3) {
        p = unpk2(aL3); q = unpk2(aH3);
        o.x = bf2_bits(__float22bfloat162_rn(p));
        o.y = bf2_bits(__float22bfloat162_rn(q));
        O[r3 * 32 + cg] = o;
    }
}

// ---------------- layer-2 gather + bias + relu + fused mean -> gsum ---------
__global__ void __launch_bounds__(256) k_gather2(const float* __restrict__ b2) {
    __shared__ float sacc[2 * HID];
    int tid = threadIdx.x;
    int w = blockIdx.x * 8 + (tid >> 5);
    int lane = tid & 31;
    float di = g_dis[w];
    int e   = g_rowptr[w];
    int end = g_rowptr[w + 1];
    const uint2* T2 = (const uint2*)g_tB;
    float sc = di * di;
    float4 acc = make_float4(0.f, 0.f, 0.f, 0.f);
    fma_bf(acc, sc, T2[w * 32 + lane]);
    int e4 = e + ((end - e) & ~3);
    for (; e < e4; e += 4) {
        uint32_t c0 = __ldg(&g_coln[e]);
        uint32_t c1 = __ldg(&g_coln[e + 1]);
        uint32_t c2 = __ldg(&g_coln[e + 2]);
        uint32_t c3 = __ldg(&g_coln[e + 3]);
        uint2 u0 = __ldg(&T2[up_src(c0) * 32 + lane]);
        uint2 u1 = __ldg(&T2[up_src(c1) * 32 + lane]);
        uint2 u2 = __ldg(&T2[up_src(c2) * 32 + lane]);
        uint2 u3 = __ldg(&T2[up_src(c3) * 32 + lane]);
        fma_bf(acc, up_nrm(c0), u0);
        fma_bf(acc, up_nrm(c1), u1);
        fma_bf(acc, up_nrm(c2), u2);
        fma_bf(acc, up_nrm(c3), u3);
    }
    for (; e < end; e++) {
        uint32_t c = __ldg(&g_coln[e]);
        fma_bf(acc, up_nrm(c), __ldg(&T2[up_src(c) * 32 + lane]));
    }
    float4 b = ((const float4*)b2)[lane];
    acc.x = fmaxf(acc.x + b.x, 0.f); acc.y = fmaxf(acc.y + b.y, 0.f);
    acc.z = fmaxf(acc.z + b.z, 0.f); acc.w = fmaxf(acc.w + b.w, 0.f);
    int half2_ = tid >> 7;
    int wi   = (tid >> 5) & 3;
    float4* s4 = (float4*)sacc;
    if (wi == 0) s4[half2_ * 32 + lane] = acc;
    __syncthreads();
    if (wi == 1) fma4(s4[half2_ * 32 + lane], 1.f, acc);
    __syncthreads();
    if (wi == 2) fma4(s4[half2_ * 32 + lane], 1.f, acc);
    __syncthreads();
    if (wi == 3) fma4(s4[half2_ * 32 + lane], 1.f, acc);
    __syncthreads();
    if (tid < 32) {
        float4 v0 = s4[tid];
        float4 v1 = s4[32 + tid];
        v0.x += v1.x; v0.y += v1.y; v0.z += v1.z; v0.w += v1.w;
        red_add_f4(&((float4*)g_gsum)[tid], v0);
    }
}

// ---------------- head ------------------------------------------------------
__global__ void __launch_bounds__(128) k_head(const float* __restrict__ eps,
                                              const float* __restrict__ Wmu, const float* __restrict__ bmu,
                                              const float* __restrict__ Wlv, const float* __restrict__ blv,
                                              const float* __restrict__ Wd1, const float* __restrict__ bd1,
                                              float* __restrict__ out) {
    __shared__ float gs[HID], zs[LAT];
    int tid = threadIdx.x;
    gs[tid] = g_gsum[tid] * (1.0f / (float)NN);
    __syncthreads();
    if (tid < LAT) {
        float mu = bmu[tid], lv = blv[tid];
#pragma unroll 4
        for (int k = 0; k < HID; k++) {
            float gk = gs[k];
            mu = fmaf(gk, Wmu[k * LAT + tid], mu);
            lv = fmaf(gk, Wlv[k * LAT + tid], lv);
        }
        out[(size_t)NN * CIN + tid] = mu;
        out[(size_t)NN * CIN + LAT + tid] = lv;
        zs[tid] = fmaf(eps[tid], expf(0.5f * lv), mu);
    }
    __syncthreads();
    float dv = bd1[tid];
#pragma unroll 4
    for (int k = 0; k < LAT; k++) dv = fmaf(zs[k], Wd1[k * HID + tid], dv);
    g_dvec[tid] = fmaxf(dv, 0.f);
}

// ---------------- decoder GEMV ----------------------------------------------
__global__ void __launch_bounds__(256) k_dec(const float* __restrict__ Wd2,
                                             const float* __restrict__ bd2,
                                             float* __restrict__ out) {
    __shared__ float ds[HID];
    int tid = threadIdx.x;
    if (tid < HID) ds[tid] = g_dvec[tid];
    __syncthreads();
    int j = blockIdx.x * 256 + tid;
    const int NC4 = NN * CIN / 4;
    if (j >= NC4) return;
    const float4* W = (const float4*)Wd2;
    float4 acc = ((const float4*)bd2)[j];
#pragma unroll 8
    for (int k = 0; k < HID; k++) {
        float dk = ds[k];
        fma4(acc, dk, W[(size_t)k * NC4 + j]);
    }
    ((float4*)out)[j] = acc;
}

// ---------------- launch ----------------------------------------------------
extern "C" void kernel_launch(void* const* d_in, const int* in_sizes, int n_in,
                              void* d_out, int out_size) {
    const float* x   = (const float*)d_in[0];
    const int*   ei  = (const int*)  d_in[1];
    const float* eps = (const float*)d_in[2];
    const float* W1  = (const float*)d_in[3];
    const float* b1  = (const float*)d_in[4];
    const float* W2  = (const float*)d_in[5];
    const float* b2  = (const float*)d_in[6];
    const float* Wmu = (const float*)d_in[7];
    const float* bmu = (const float*)d_in[8];
    const float* Wlv = (const float*)d_in[9];
    const float* blv = (const float*)d_in[10];
    const float* Wd1 = (const float*)d_in[11];
    const float* bd1 = (const float*)d_in[12];
    const float* Wd2 = (const float*)d_in[13];
    const float* bd2 = (const float*)d_in[14];
    float* out = (float*)d_out;

    (void)in_sizes; (void)n_in; (void)out_size;

    const int EQ = EE / 4;
    k_init   <<<(NN * CIN / 2 + 255) / 256, 256>>>(x);
    k_deg    <<<(EQ + 255) / 256, 256>>>(ei + EE);
    k_scan   <<<1, 1024>>>();
    k_fill   <<<(EQ + 255) / 256, 256>>>(ei);
    k_gather1<<<NN * 32 / 256, 256>>>();
    k_layer1 <<<NN / 8, 256>>>(W1, b1);
    k_gemm2  <<<(NN + 31) / 32, 256>>>(W2);
    k_gather2<<<NN / 8, 256>>>(b2);
    k_head   <<<1, 128>>>(eps, Wmu, bmu, Wlv, blv, Wd1, bd1, out);
    k_dec    <<<(NN * CIN / 4 + 255) / 256, 256>>>(Wd2, bd2, out);
}

// round 11
// speedup vs baseline: 1.1590x; 1.1590x over previous
#include <cuda_runtime.h>
#include <cuda_bf16.h>
#include <math.h>
#include <stdint.h>

#define NN   50000
#define EE   1600000
#define CIN  32
#define HID  128
#define LAT  64
#define HID4 (HID/4)
#define CIN4 (CIN/4)

// ---------------- scratch (device globals; no allocations allowed) ----------
__device__ int   g_ideg[NN];                 // in-degree (edges only)
__device__ int   g_cnt[NN];                  // fill cursors (init = rowptr)
__device__ int   g_rowptr[NN + 1];           // CSR row pointers
__device__ __align__(16) int2  g_coln[EE];   // per-edge {src, bits(nrm)}
__device__ __align__(16) float g_dis[NN];
__device__ __align__(16) __nv_bfloat16 g_xh[NN * CIN];   // bf16 copy of x
__device__ __align__(16) float g_aggx[NN * CIN];         // layer-1 GCN input
__device__ __align__(16) float g_bufA[NN * HID];         // h1
__device__ __align__(16) __nv_bfloat16 g_tB[NN * HID];   // t2 = h1@W2, bf16
__device__ __align__(16) float g_gsum[HID];
__device__ int  g_dcnt;                      // # nonzero entries of d
__device__ __align__(16) int2 g_dnz[HID];    // compacted {k, bits(d[k])}

__device__ __forceinline__ void fma4(float4& acc, float s, const float4& v) {
    acc.x = fmaf(s, v.x, acc.x);
    acc.y = fmaf(s, v.y, acc.y);
    acc.z = fmaf(s, v.z, acc.z);
    acc.w = fmaf(s, v.w, acc.w);
}

__device__ __forceinline__ uint32_t bf2_bits(__nv_bfloat162 v) {
    return *reinterpret_cast<uint32_t*>(&v);
}

__device__ __forceinline__ void fma_bf(float4& acc, float n, uint2 u) {
    __nv_bfloat162 lo = *reinterpret_cast<__nv_bfloat162*>(&u.x);
    __nv_bfloat162 hi = *reinterpret_cast<__nv_bfloat162*>(&u.y);
    float2 f0 = __bfloat1622float2(lo);
    float2 f1 = __bfloat1622float2(hi);
    acc.x = fmaf(n, f0.x, acc.x); acc.y = fmaf(n, f0.y, acc.y);
    acc.z = fmaf(n, f1.x, acc.z); acc.w = fmaf(n, f1.y, acc.w);
}

__device__ __forceinline__ void red_add_f4(float4* p, float4 v) {
    asm volatile("red.global.add.v4.f32 [%0], {%1,%2,%3,%4};"
                 :: "l"(p), "f"(v.x), "f"(v.y), "f"(v.z), "f"(v.w)
                 : "memory");
}

// ---------------- init: zero ideg/gsum + convert x -> bf16 ------------------
__global__ void k_init(const float* __restrict__ x) {
    int i = blockIdx.x * 256 + threadIdx.x;
    if (i < NN)  g_ideg[i] = 0;
    if (i < HID) g_gsum[i] = 0.0f;
    if (i < NN * CIN / 2) {
        float2 v = ((const float2*)x)[i];
        ((__nv_bfloat162*)g_xh)[i] = __float22bfloat162_rn(v);
    }
}

// ---------------- integer degree over dst: 4 edges / thread ----------------
__global__ void k_deg(const int* __restrict__ dst) {
    int e0 = (blockIdx.x * 256 + threadIdx.x) * 4;
    if (e0 >= EE) return;                      // EE % 4 == 0
    int4 d4 = *(const int4*)(dst + e0);
    atomicAdd(&g_ideg[d4.x], 1);
    atomicAdd(&g_ideg[d4.y], 1);
    atomicAdd(&g_ideg[d4.z], 1);
    atomicAdd(&g_ideg[d4.w], 1);
}

// ---------------- single-block scan -> rowptr, cnt(=rowptr), dis ------------
__global__ void __launch_bounds__(1024) k_scan() {
    const int CH = 49;                         // ceil(50000/1024)
    int tid = threadIdx.x;
    int base = tid * CH;
    int local = 0;
#pragma unroll
    for (int j = 0; j < CH; j++) {
        int i = base + j;
        if (i < NN) local += g_ideg[i];
    }
    __shared__ int wsum[32];
    int lane = tid & 31, wid = tid >> 5;
    int inc = local;
#pragma unroll
    for (int off = 1; off < 32; off <<= 1) {
        int t = __shfl_up_sync(0xffffffffu, inc, off);
        if (lane >= off) inc += t;
    }
    if (lane == 31) wsum[wid] = inc;
    __syncthreads();
    if (wid == 0) {
        int v = wsum[lane];
#pragma unroll
        for (int off = 1; off < 32; off <<= 1) {
            int t = __shfl_up_sync(0xffffffffu, v, off);
            if (lane >= off) v += t;
        }
        wsum[lane] = v;
    }
    __syncthreads();
    int run = inc - local + (wid > 0 ? wsum[wid - 1] : 0);   // exclusive prefix
#pragma unroll
    for (int j = 0; j < CH; j++) {
        int i = base + j;
        if (i < NN) {
            int d = g_ideg[i];
            g_rowptr[i] = run;
            g_cnt[i]    = run;                               // fill cursor base
            g_dis[i] = rsqrtf((float)(d + 1));               // +1 self loop
            run += d;
        }
    }
    if (tid == 1023) g_rowptr[NN] = run;
}

// ---------------- CSR fill: 4 edges/thread, store {src, nrm} ----------------
__global__ void k_fill(const int* __restrict__ ei) {
    int e0 = (blockIdx.x * 256 + threadIdx.x) * 4;
    if (e0 >= EE) return;
    int4 s4 = *(const int4*)(ei + e0);
    int4 d4 = *(const int4*)(ei + EE + e0);
    float a0 = __ldg(&g_dis[s4.x]) * __ldg(&g_dis[d4.x]);
    float a1 = __ldg(&g_dis[s4.y]) * __ldg(&g_dis[d4.y]);
    float a2 = __ldg(&g_dis[s4.z]) * __ldg(&g_dis[d4.z]);
    float a3 = __ldg(&g_dis[s4.w]) * __ldg(&g_dis[d4.w]);
    int p0 = atomicAdd(&g_cnt[d4.x], 1);       // global slot directly
    int p1 = atomicAdd(&g_cnt[d4.y], 1);
    int p2 = atomicAdd(&g_cnt[d4.z], 1);
    int p3 = atomicAdd(&g_cnt[d4.w], 1);
    g_coln[p0] = make_int2(s4.x, __float_as_int(a0));
    g_coln[p1] = make_int2(s4.y, __float_as_int(a1));
    g_coln[p2] = make_int2(s4.z, __float_as_int(a2));
    g_coln[p3] = make_int2(s4.w, __float_as_int(a3));
}

// ---------------- layer-1 gather (32 cols, bf16 payload), warp/node ---------
__global__ void __launch_bounds__(256) k_gather1() {
    int w = (blockIdx.x * 256 + threadIdx.x) >> 5;
    int lane = threadIdx.x & 31;
    if (w >= NN) return;
    float di = g_dis[w];
    int e   = g_rowptr[w];
    int end = g_rowptr[w + 1];
    float acc = __bfloat162float(g_xh[w * CIN + lane]) * di * di;
    int e4 = e + ((end - e) & ~3);
    for (; e < e4; e += 4) {
        int2 c0 = __ldg(&g_coln[e]);
        int2 c1 = __ldg(&g_coln[e + 1]);
        int2 c2 = __ldg(&g_coln[e + 2]);
        int2 c3 = __ldg(&g_coln[e + 3]);
        float v0 = __bfloat162float(g_xh[c0.x * CIN + lane]);
        float v1 = __bfloat162float(g_xh[c1.x * CIN + lane]);
        float v2 = __bfloat162float(g_xh[c2.x * CIN + lane]);
        float v3 = __bfloat162float(g_xh[c3.x * CIN + lane]);
        acc = fmaf(v0, __int_as_float(c0.y), acc);
        acc = fmaf(v1, __int_as_float(c1.y), acc);
        acc = fmaf(v2, __int_as_float(c2.y), acc);
        acc = fmaf(v3, __int_as_float(c3.y), acc);
    }
    for (; e < end; e++) {
        int2 c = __ldg(&g_coln[e]);
        acc = fmaf(__bfloat162float(g_xh[c.x * CIN + lane]),
                   __int_as_float(c.y), acc);
    }
    g_aggx[w * CIN + lane] = acc;
}

// ---------------- layer 1: h1 = relu(aggx @ W1 + b1) -> bufA ----------------
__global__ void __launch_bounds__(256) k_layer1(const float* __restrict__ W1,
                                                const float* __restrict__ b1) {
    __shared__ float sW[CIN * HID];   // 16 KB
    __shared__ float sv[8 * CIN];
    int tid = threadIdx.x;
    int row0 = blockIdx.x * 8;
    for (int i = tid; i < CIN * HID; i += 256) sW[i] = W1[i];
    sv[tid] = g_aggx[row0 * CIN + tid];
    __syncthreads();
    int r = tid >> 5, cg = tid & 31;
    float4 acc = ((const float4*)b1)[cg];
    const float4* sW4 = (const float4*)sW;
#pragma unroll
    for (int k = 0; k < CIN; k++) {
        float a = sv[r * CIN + k];
        fma4(acc, a, sW4[k * HID4 + cg]);
    }
    acc.x = fmaxf(acc.x, 0.f); acc.y = fmaxf(acc.y, 0.f);
    acc.z = fmaxf(acc.z, 0.f); acc.w = fmaxf(acc.w, 0.f);
    ((float4*)g_bufA)[(row0 + r) * HID4 + cg] = acc;
}

// ---------------- GEMM2: tB(bf16) = bufA @ W2 -------------------------------
__global__ void __launch_bounds__(256) k_gemm2(const float* __restrict__ W2) {
    int tid = threadIdx.x;
    int cg = tid & 31, rl = tid >> 5;
    int rbase = blockIdx.x * 32 + rl;
    int r0 = rbase, r1 = rbase + 8, r2 = rbase + 16, r3 = rbase + 24;
    bool v0 = r0 < NN, v1 = r1 < NN, v2 = r2 < NN, v3 = r3 < NN;
    const float4* W4 = (const float4*)W2;
    const float4* A4 = (const float4*)g_bufA;
    float4 zf = make_float4(0.f, 0.f, 0.f, 0.f);
    float4 a0 = zf, a1 = zf, a2 = zf, a3 = zf;
#pragma unroll 4
    for (int k4 = 0; k4 < HID4; k4++) {
        float4 x0 = v0 ? __ldg(&A4[r0 * HID4 + k4]) : zf;
        float4 x1 = v1 ? __ldg(&A4[r1 * HID4 + k4]) : zf;
        float4 x2 = v2 ? __ldg(&A4[r2 * HID4 + k4]) : zf;
        float4 x3 = v3 ? __ldg(&A4[r3 * HID4 + k4]) : zf;
        float4 w0 = __ldg(&W4[(k4 * 4 + 0) * HID4 + cg]);
        float4 w1 = __ldg(&W4[(k4 * 4 + 1) * HID4 + cg]);
        float4 w2 = __ldg(&W4[(k4 * 4 + 2) * HID4 + cg]);
        float4 w3 = __ldg(&W4[(k4 * 4 + 3) * HID4 + cg]);
        fma4(a0, x0.x, w0); fma4(a0, x0.y, w1); fma4(a0, x0.z, w2); fma4(a0, x0.w, w3);
        fma4(a1, x1.x, w0); fma4(a1, x1.y, w1); fma4(a1, x1.z, w2); fma4(a1, x1.w, w3);
        fma4(a2, x2.x, w0); fma4(a2, x2.y, w1); fma4(a2, x2.z, w2); fma4(a2, x2.w, w3);
        fma4(a3, x3.x, w0); fma4(a3, x3.y, w1); fma4(a3, x3.z, w2); fma4(a3, x3.w, w3);
    }
    uint2* O = (uint2*)g_tB;                   // 4 bf16 per uint2
    uint2 o;
    if (v0) {
        o.x = bf2_bits(__float22bfloat162_rn(make_float2(a0.x, a0.y)));
        o.y = bf2_bits(__float22bfloat162_rn(make_float2(a0.z, a0.w)));
        O[r0 * 32 + cg] = o;
    }
    if (v1) {
        o.x = bf2_bits(__float22bfloat162_rn(make_float2(a1.x, a1.y)));
        o.y = bf2_bits(__float22bfloat162_rn(make_float2(a1.z, a1.w)));
        O[r1 * 32 + cg] = o;
    }
    if (v2) {
        o.x = bf2_bits(__float22bfloat162_rn(make_float2(a2.x, a2.y)));
        o.y = bf2_bits(__float22bfloat162_rn(make_float2(a2.z, a2.w)));
        O[r2 * 32 + cg] = o;
    }
    if (v3) {
        o.x = bf2_bits(__float22bfloat162_rn(make_float2(a3.x, a3.y)));
        o.y = bf2_bits(__float22bfloat162_rn(make_float2(a3.z, a3.w)));
        O[r3 * 32 + cg] = o;
    }
}

// ---------------- layer-2 gather + bias + relu + fused mean -> gsum ---------
__global__ void __launch_bounds__(256) k_gather2(const float* __restrict__ b2) {
    __shared__ float sacc[2 * HID];
    int tid = threadIdx.x;
    int w = blockIdx.x * 8 + (tid >> 5);
    int lane = tid & 31;
    float di = g_dis[w];
    int e   = g_rowptr[w];
    int end = g_rowptr[w + 1];
    const uint2* T2 = (const uint2*)g_tB;
    float sc = di * di;
    float4 acc = make_float4(0.f, 0.f, 0.f, 0.f);
    fma_bf(acc, sc, T2[w * 32 + lane]);
    int e4 = e + ((end - e) & ~3);
    for (; e < e4; e += 4) {
        int2 c0 = __ldg(&g_coln[e]);
        int2 c1 = __ldg(&g_coln[e + 1]);
        int2 c2 = __ldg(&g_coln[e + 2]);
        int2 c3 = __ldg(&g_coln[e + 3]);
        uint2 u0 = __ldg(&T2[c0.x * 32 + lane]);
        uint2 u1 = __ldg(&T2[c1.x * 32 + lane]);
        uint2 u2 = __ldg(&T2[c2.x * 32 + lane]);
        uint2 u3 = __ldg(&T2[c3.x * 32 + lane]);
        fma_bf(acc, __int_as_float(c0.y), u0);
        fma_bf(acc, __int_as_float(c1.y), u1);
        fma_bf(acc, __int_as_float(c2.y), u2);
        fma_bf(acc, __int_as_float(c3.y), u3);
    }
    for (; e < end; e++) {
        int2 c = __ldg(&g_coln[e]);
        fma_bf(acc, __int_as_float(c.y), __ldg(&T2[c.x * 32 + lane]));
    }
    float4 b = ((const float4*)b2)[lane];
    acc.x = fmaxf(acc.x + b.x, 0.f); acc.y = fmaxf(acc.y + b.y, 0.f);
    acc.z = fmaxf(acc.z + b.z, 0.f); acc.w = fmaxf(acc.w + b.w, 0.f);
    int half = tid >> 7;
    int wi   = (tid >> 5) & 3;
    float4* s4 = (float4*)sacc;
    if (wi == 0) s4[half * 32 + lane] = acc;
    __syncthreads();
    if (wi == 1) fma4(s4[half * 32 + lane], 1.f, acc);
    __syncthreads();
    if (wi == 2) fma4(s4[half * 32 + lane], 1.f, acc);
    __syncthreads();
    if (wi == 3) fma4(s4[half * 32 + lane], 1.f, acc);
    __syncthreads();
    if (tid < 32) {
        float4 v0 = s4[tid];
        float4 v1 = s4[32 + tid];
        v0.x += v1.x; v0.y += v1.y; v0.z += v1.z; v0.w += v1.w;
        red_add_f4(&((float4*)g_gsum)[tid], v0);
    }
}

// ---------------- head: mu, logvar (to out), z, d -> compacted nonzeros -----
__global__ void __launch_bounds__(128) k_head(const float* __restrict__ eps,
                                              const float* __restrict__ Wmu, const float* __restrict__ bmu,
                                              const float* __restrict__ Wlv, const float* __restrict__ blv,
                                              const float* __restrict__ Wd1, const float* __restrict__ bd1,
                                              float* __restrict__ out) {
    __shared__ float gs[HID], zs[LAT];
    __shared__ int wbase[4];
    int tid = threadIdx.x;
    int lane = tid & 31, wid = tid >> 5;
    gs[tid] = g_gsum[tid] * (1.0f / (float)NN);
    __syncthreads();
    if (tid < LAT) {
        float mu = bmu[tid], lv = blv[tid];
#pragma unroll 4
        for (int k = 0; k < HID; k++) {
            float gk = gs[k];
            mu = fmaf(gk, Wmu[k * LAT + tid], mu);
            lv = fmaf(gk, Wlv[k * LAT + tid], lv);
        }
        out[(size_t)NN * CIN + tid] = mu;
        out[(size_t)NN * CIN + LAT + tid] = lv;
        zs[tid] = fmaf(eps[tid], expf(0.5f * lv), mu);
    }
    __syncthreads();
    float dv = bd1[tid];
#pragma unroll 4
    for (int k = 0; k < LAT; k++) dv = fmaf(zs[k], Wd1[k * HID + tid], dv);
    dv = fmaxf(dv, 0.f);
    // deterministic compaction of nonzero entries (ballot + popc prefix)
    unsigned m = __ballot_sync(0xffffffffu, dv > 0.f);
    if (lane == 0) wbase[wid] = __popc(m);
    __syncthreads();
    if (tid == 0) {
        int s = 0;
#pragma unroll
        for (int i = 0; i < 4; i++) { int t = wbase[i]; wbase[i] = s; s += t; }
        g_dcnt = s;
    }
    __syncthreads();
    if (dv > 0.f) {
        int p = wbase[wid] + __popc(m & ((1u << lane) - 1u));
        g_dnz[p] = make_int2(tid, __float_as_int(dv));
    }
}

// ---------------- decoder GEMV over NONZERO d rows only ---------------------
__global__ void __launch_bounds__(256) k_dec(const float* __restrict__ Wd2,
                                             const float* __restrict__ bd2,
                                             float* __restrict__ out) {
    __shared__ int2 sd[HID];
    __shared__ int  scnt;
    int tid = threadIdx.x;
    if (tid == 0) scnt = g_dcnt;
    if (tid < HID) sd[tid] = g_dnz[tid];
    __syncthreads();
    int cnt = scnt;
    int j = blockIdx.x * 256 + tid;              // float4 column index
    const int NC4 = NN * CIN / 4;                // 400000
    if (j >= NC4) return;
    const float4* W = (const float4*)Wd2;
    float4 acc = ((const float4*)bd2)[j];
#pragma unroll 4
    for (int t = 0; t < cnt; t++) {
        int2 e = sd[t];
        float dk = __int_as_float(e.y);
        float4 w = __ldcs(&W[(size_t)e.x * NC4 + j]);   // streaming, read-once
        fma4(acc, dk, w);
    }
    ((float4*)out)[j] = acc;
}

// ---------------- launch ----------------------------------------------------
extern "C" void kernel_launch(void* const* d_in, const int* in_sizes, int n_in,
                              void* d_out, int out_size) {
    const float* x   = (const float*)d_in[0];
    const int*   ei  = (const int*)  d_in[1];
    const float* eps = (const float*)d_in[2];
    const float* W1  = (const float*)d_in[3];
    const float* b1  = (const float*)d_in[4];
    const float* W2  = (const float*)d_in[5];
    const float* b2  = (const float*)d_in[6];
    const float* Wmu = (const float*)d_in[7];
    const float* bmu = (const float*)d_in[8];
    const float* Wlv = (const float*)d_in[9];
    const float* blv = (const float*)d_in[10];
    const float* Wd1 = (const float*)d_in[11];
    const float* bd1 = (const float*)d_in[12];
    const float* Wd2 = (const float*)d_in[13];
    const float* bd2 = (const float*)d_in[14];
    float* out = (float*)d_out;

    (void)in_sizes; (void)n_in; (void)out_size;

    const int EQ = EE / 4;
    k_init   <<<(NN * CIN / 2 + 255) / 256, 256>>>(x);
    k_deg    <<<(EQ + 255) / 256, 256>>>(ei + EE);
    k_scan   <<<1, 1024>>>();
    k_fill   <<<(EQ + 255) / 256, 256>>>(ei);
    k_gather1<<<NN * 32 / 256, 256>>>();
    k_layer1 <<<NN / 8, 256>>>(W1, b1);
    k_gemm2  <<<(NN + 31) / 32, 256>>>(W2);
    k_gather2<<<NN / 8, 256>>>(b2);
    k_head   <<<1, 128>>>(eps, Wmu, bmu, Wlv, blv, Wd1, bd1, out);
    k_dec    <<<(NN * CIN / 4 + 255) / 256, 256>>>(Wd2, bd2, out);
}

// round 12
// speedup vs baseline: 1.1704x; 1.0098x over previous
#include <cuda_runtime.h>
#include <cuda_bf16.h>
#include <cuda_fp16.h>
#include <math.h>
#include <stdint.h>

#define NN   50000
#define EE   1600000
#define CIN  32
#define HID  128
#define LAT  64
#define HID4 (HID/4)
#define CIN4 (CIN/4)

// ---------------- scratch (device globals; no allocations allowed) ----------
__device__ int   g_ideg[NN];                 // in-degree (edges only)
__device__ int   g_cnt[NN];                  // fill cursors (init = rowptr)
__device__ int   g_rowptr[NN + 1];           // CSR row pointers
__device__ __align__(16) uint32_t g_coln[EE]; // {src:16 | half(nrm):16}
__device__ __align__(16) float g_dis[NN];
__device__ __align__(16) __nv_bfloat16 g_xh[NN * CIN];   // bf16 copy of x
__device__ __align__(16) float g_bufA[NN * HID];         // h1
__device__ __align__(16) __nv_bfloat16 g_tB[NN * HID];   // t2 = h1@W2, bf16
__device__ __align__(16) float g_gsum[HID];
__device__ int  g_dcnt;                      // # nonzero entries of d
__device__ __align__(16) int2 g_dnz[HID];    // compacted {k, bits(d[k])}

__device__ __forceinline__ void fma4(float4& acc, float s, const float4& v) {
    acc.x = fmaf(s, v.x, acc.x);
    acc.y = fmaf(s, v.y, acc.y);
    acc.z = fmaf(s, v.z, acc.z);
    acc.w = fmaf(s, v.w, acc.w);
}

__device__ __forceinline__ uint32_t bf2_bits(__nv_bfloat162 v) {
    return *reinterpret_cast<uint32_t*>(&v);
}

__device__ __forceinline__ void fma_bf(float4& acc, float n, uint2 u) {
    __nv_bfloat162 lo = *reinterpret_cast<__nv_bfloat162*>(&u.x);
    __nv_bfloat162 hi = *reinterpret_cast<__nv_bfloat162*>(&u.y);
    float2 f0 = __bfloat1622float2(lo);
    float2 f1 = __bfloat1622float2(hi);
    acc.x = fmaf(n, f0.x, acc.x); acc.y = fmaf(n, f0.y, acc.y);
    acc.z = fmaf(n, f1.x, acc.z); acc.w = fmaf(n, f1.y, acc.w);
}

__device__ __forceinline__ void red_add_f4(float4* p, float4 v) {
    asm volatile("red.global.add.v4.f32 [%0], {%1,%2,%3,%4};"
                 :: "l"(p), "f"(v.x), "f"(v.y), "f"(v.z), "f"(v.w)
                 : "memory");
}

__device__ __forceinline__ uint32_t pack_sn(int s, float nrm) {
    return (uint32_t)s | ((uint32_t)__half_as_ushort(__float2half_rn(nrm)) << 16);
}
__device__ __forceinline__ int up_src(uint32_t c) { return (int)(c & 0xffffu); }
__device__ __forceinline__ float up_nrm(uint32_t c) {
    return __half2float(__ushort_as_half((unsigned short)(c >> 16)));
}

// ---------------- init: zero ideg/gsum + convert x -> bf16 ------------------
__global__ void k_init(const float* __restrict__ x) {
    int i = blockIdx.x * 256 + threadIdx.x;
    if (i < NN)  g_ideg[i] = 0;
    if (i < HID) g_gsum[i] = 0.0f;
    if (i < NN * CIN / 2) {
        float2 v = ((const float2*)x)[i];
        ((__nv_bfloat162*)g_xh)[i] = __float22bfloat162_rn(v);
    }
}

// ---------------- integer degree over dst: 4 edges / thread ----------------
__global__ void k_deg(const int* __restrict__ dst) {
    int e0 = (blockIdx.x * 256 + threadIdx.x) * 4;
    if (e0 >= EE) return;                      // EE % 4 == 0
    int4 d4 = *(const int4*)(dst + e0);
    atomicAdd(&g_ideg[d4.x], 1);
    atomicAdd(&g_ideg[d4.y], 1);
    atomicAdd(&g_ideg[d4.z], 1);
    atomicAdd(&g_ideg[d4.w], 1);
}

// ---------------- single-block scan -> rowptr, cnt(=rowptr), dis ------------
__global__ void __launch_bounds__(1024) k_scan() {
    const int CH = 49;                         // ceil(50000/1024)
    int tid = threadIdx.x;
    int base = tid * CH;
    int local = 0;
#pragma unroll
    for (int j = 0; j < CH; j++) {
        int i = base + j;
        if (i < NN) local += g_ideg[i];
    }
    __shared__ int wsum[32];
    int lane = tid & 31, wid = tid >> 5;
    int inc = local;
#pragma unroll
    for (int off = 1; off < 32; off <<= 1) {
        int t = __shfl_up_sync(0xffffffffu, inc, off);
        if (lane >= off) inc += t;
    }
    if (lane == 31) wsum[wid] = inc;
    __syncthreads();
    if (wid == 0) {
        int v = wsum[lane];
#pragma unroll
        for (int off = 1; off < 32; off <<= 1) {
            int t = __shfl_up_sync(0xffffffffu, v, off);
            if (lane >= off) v += t;
        }
        wsum[lane] = v;
    }
    __syncthreads();
    int run = inc - local + (wid > 0 ? wsum[wid - 1] : 0);   // exclusive prefix
#pragma unroll
    for (int j = 0; j < CH; j++) {
        int i = base + j;
        if (i < NN) {
            int d = g_ideg[i];
            g_rowptr[i] = run;
            g_cnt[i]    = run;                               // fill cursor base
            g_dis[i] = rsqrtf((float)(d + 1));               // +1 self loop
            run += d;
        }
    }
    if (tid == 1023) g_rowptr[NN] = run;
}

// ---------------- CSR fill: 4 edges/thread, packed 4B entries ---------------
__global__ void k_fill(const int* __restrict__ ei) {
    int e0 = (blockIdx.x * 256 + threadIdx.x) * 4;
    if (e0 >= EE) return;
    int4 s4 = *(const int4*)(ei + e0);
    int4 d4 = *(const int4*)(ei + EE + e0);
    float a0 = __ldg(&g_dis[s4.x]) * __ldg(&g_dis[d4.x]);
    float a1 = __ldg(&g_dis[s4.y]) * __ldg(&g_dis[d4.y]);
    float a2 = __ldg(&g_dis[s4.z]) * __ldg(&g_dis[d4.z]);
    float a3 = __ldg(&g_dis[s4.w]) * __ldg(&g_dis[d4.w]);
    int p0 = atomicAdd(&g_cnt[d4.x], 1);       // global slot directly
    int p1 = atomicAdd(&g_cnt[d4.y], 1);
    int p2 = atomicAdd(&g_cnt[d4.z], 1);
    int p3 = atomicAdd(&g_cnt[d4.w], 1);
    g_coln[p0] = pack_sn(s4.x, a0);
    g_coln[p1] = pack_sn(s4.y, a1);
    g_coln[p2] = pack_sn(s4.z, a2);
    g_coln[p3] = pack_sn(s4.w, a3);
}

// ---------------- FUSED layer-1: gather (warp/node) + matmul + relu ---------
__global__ void __launch_bounds__(256) k_g1l1(const float* __restrict__ W1,
                                              const float* __restrict__ b1) {
    __shared__ float sW[CIN * HID];   // 16 KB
    __shared__ float sv[8 * CIN];
    int tid = threadIdx.x;
    int r = tid >> 5, lane = tid & 31;
    int w = blockIdx.x * 8 + r;                  // NN % 8 == 0
    for (int i = tid; i < CIN * HID; i += 256) sW[i] = W1[i];
    // gather node w, column lane
    float di = g_dis[w];
    int e   = g_rowptr[w];
    int end = g_rowptr[w + 1];
    float acc = __bfloat162float(g_xh[w * CIN + lane]) * di * di;
    int e4 = e + ((end - e) & ~3);
    for (; e < e4; e += 4) {
        uint32_t c0 = __ldg(&g_coln[e]);
        uint32_t c1 = __ldg(&g_coln[e + 1]);
        uint32_t c2 = __ldg(&g_coln[e + 2]);
        uint32_t c3 = __ldg(&g_coln[e + 3]);
        float v0 = __bfloat162float(g_xh[up_src(c0) * CIN + lane]);
        float v1 = __bfloat162float(g_xh[up_src(c1) * CIN + lane]);
        float v2 = __bfloat162float(g_xh[up_src(c2) * CIN + lane]);
        float v3 = __bfloat162float(g_xh[up_src(c3) * CIN + lane]);
        acc = fmaf(v0, up_nrm(c0), acc);
        acc = fmaf(v1, up_nrm(c1), acc);
        acc = fmaf(v2, up_nrm(c2), acc);
        acc = fmaf(v3, up_nrm(c3), acc);
    }
    for (; e < end; e++) {
        uint32_t c = __ldg(&g_coln[e]);
        acc = fmaf(__bfloat162float(g_xh[up_src(c) * CIN + lane]), up_nrm(c), acc);
    }
    sv[tid] = acc;                               // tid == r*32 + lane
    __syncthreads();                             // sW + sv ready
    // matmul: thread (r, cg=lane) -> row w, cols 4*cg..4*cg+3
    float4 a4 = ((const float4*)b1)[lane];
    const float4* sW4 = (const float4*)sW;
#pragma unroll
    for (int k = 0; k < CIN; k++) {
        fma4(a4, sv[r * CIN + k], sW4[k * HID4 + lane]);
    }
    a4.x = fmaxf(a4.x, 0.f); a4.y = fmaxf(a4.y, 0.f);
    a4.z = fmaxf(a4.z, 0.f); a4.w = fmaxf(a4.w, 0.f);
    ((float4*)g_bufA)[w * HID4 + lane] = a4;
}

// ---------------- GEMM2: tB(bf16) = bufA @ W2 -------------------------------
__global__ void __launch_bounds__(256) k_gemm2(const float* __restrict__ W2) {
    int tid = threadIdx.x;
    int cg = tid & 31, rl = tid >> 5;
    int rbase = blockIdx.x * 32 + rl;
    int r0 = rbase, r1 = rbase + 8, r2 = rbase + 16, r3 = rbase + 24;
    bool v0 = r0 < NN, v1 = r1 < NN, v2 = r2 < NN, v3 = r3 < NN;
    const float4* W4 = (const float4*)W2;
    const float4* A4 = (const float4*)g_bufA;
    float4 zf = make_float4(0.f, 0.f, 0.f, 0.f);
    float4 a0 = zf, a1 = zf, a2 = zf, a3 = zf;
#pragma unroll 4
    for (int k4 = 0; k4 < HID4; k4++) {
        float4 x0 = v0 ? __ldg(&A4[r0 * HID4 + k4]) : zf;
        float4 x1 = v1 ? __ldg(&A4[r1 * HID4 + k4]) : zf;
        float4 x2 = v2 ? __ldg(&A4[r2 * HID4 + k4]) : zf;
        float4 x3 = v3 ? __ldg(&A4[r3 * HID4 + k4]) : zf;
        float4 w0 = __ldg(&W4[(k4 * 4 + 0) * HID4 + cg]);
        float4 w1 = __ldg(&W4[(k4 * 4 + 1) * HID4 + cg]);
        float4 w2 = __ldg(&W4[(k4 * 4 + 2) * HID4 + cg]);
        float4 w3 = __ldg(&W4[(k4 * 4 + 3) * HID4 + cg]);
        fma4(a0, x0.x, w0); fma4(a0, x0.y, w1); fma4(a0, x0.z, w2); fma4(a0, x0.w, w3);
        fma4(a1, x1.x, w0); fma4(a1, x1.y, w1); fma4(a1, x1.z, w2); fma4(a1, x1.w, w3);
        fma4(a2, x2.x, w0); fma4(a2, x2.y, w1); fma4(a2, x2.z, w2); fma4(a2, x2.w, w3);
        fma4(a3, x3.x, w0); fma4(a3, x3.y, w1); fma4(a3, x3.z, w2); fma4(a3, x3.w, w3);
    }
    uint2* O = (uint2*)g_tB;                   // 4 bf16 per uint2
    uint2 o;
    if (v0) {
        o.x = bf2_bits(__float22bfloat162_rn(make_float2(a0.x, a0.y)));
        o.y = bf2_bits(__float22bfloat162_rn(make_float2(a0.z, a0.w)));
        O[r0 * 32 + cg] = o;
    }
    if (v1) {
        o.x = bf2_bits(__float22bfloat162_rn(make_float2(a1.x, a1.y)));
        o.y = bf2_bits(__float22bfloat162_rn(make_float2(a1.z, a1.w)));
        O[r1 * 32 + cg] = o;
    }
    if (v2) {
        o.x = bf2_bits(__float22bfloat162_rn(make_float2(a2.x, a2.y)));
        o.y = bf2_bits(__float22bfloat162_rn(make_float2(a2.z, a2.w)));
        O[r2 * 32 + cg] = o;
    }
    if (v3) {
        o.x = bf2_bits(__float22bfloat162_rn(make_float2(a3.x, a3.y)));
        o.y = bf2_bits(__float22bfloat162_rn(make_float2(a3.z, a3.w)));
        O[r3 * 32 + cg] = o;
    }
}

// ---------------- layer-2 gather + bias + relu + fused mean -> gsum ---------
__global__ void __launch_bounds__(256) k_gather2(const float* __restrict__ b2) {
    __shared__ float sacc[2 * HID];
    int tid = threadIdx.x;
    int w = blockIdx.x * 8 + (tid >> 5);
    int lane = tid & 31;
    float di = g_dis[w];
    int e   = g_rowptr[w];
    int end = g_rowptr[w + 1];
    const uint2* T2 = (const uint2*)g_tB;
    float sc = di * di;
    float4 acc = make_float4(0.f, 0.f, 0.f, 0.f);
    fma_bf(acc, sc, T2[w * 32 + lane]);
    int e4 = e + ((end - e) & ~3);
    for (; e < e4; e += 4) {
        uint32_t c0 = __ldg(&g_coln[e]);
        uint32_t c1 = __ldg(&g_coln[e + 1]);
        uint32_t c2 = __ldg(&g_coln[e + 2]);
        uint32_t c3 = __ldg(&g_coln[e + 3]);
        uint2 u0 = __ldg(&T2[up_src(c0) * 32 + lane]);
        uint2 u1 = __ldg(&T2[up_src(c1) * 32 + lane]);
        uint2 u2 = __ldg(&T2[up_src(c2) * 32 + lane]);
        uint2 u3 = __ldg(&T2[up_src(c3) * 32 + lane]);
        fma_bf(acc, up_nrm(c0), u0);
        fma_bf(acc, up_nrm(c1), u1);
        fma_bf(acc, up_nrm(c2), u2);
        fma_bf(acc, up_nrm(c3), u3);
    }
    for (; e < end; e++) {
        uint32_t c = __ldg(&g_coln[e]);
        fma_bf(acc, up_nrm(c), __ldg(&T2[up_src(c) * 32 + lane]));
    }
    float4 b = ((const float4*)b2)[lane];
    acc.x = fmaxf(acc.x + b.x, 0.f); acc.y = fmaxf(acc.y + b.y, 0.f);
    acc.z = fmaxf(acc.z + b.z, 0.f); acc.w = fmaxf(acc.w + b.w, 0.f);
    int half = tid >> 7;
    int wi   = (tid >> 5) & 3;
    float4* s4 = (float4*)sacc;
    if (wi == 0) s4[half * 32 + lane] = acc;
    __syncthreads();
    if (wi == 1) fma4(s4[half * 32 + lane], 1.f, acc);
    __syncthreads();
    if (wi == 2) fma4(s4[half * 32 + lane], 1.f, acc);
    __syncthreads();
    if (wi == 3) fma4(s4[half * 32 + lane], 1.f, acc);
    __syncthreads();
    if (tid < 32) {
        float4 v0 = s4[tid];
        float4 v1 = s4[32 + tid];
        v0.x += v1.x; v0.y += v1.y; v0.z += v1.z; v0.w += v1.w;
        red_add_f4(&((float4*)g_gsum)[tid], v0);
    }
}

// ---------------- head: mu, logvar (to out), z, d -> compacted nonzeros -----
__global__ void __launch_bounds__(128) k_head(const float* __restrict__ eps,
                                              const float* __restrict__ Wmu, const float* __restrict__ bmu,
                                              const float* __restrict__ Wlv, const float* __restrict__ blv,
                                              const float* __restrict__ Wd1, const float* __restrict__ bd1,
                                              float* __restrict__ out) {
    __shared__ float gs[HID], zs[LAT];
    __shared__ int wbase[4];
    int tid = threadIdx.x;
    int lane = tid & 31, wid = tid >> 5;
    gs[tid] = g_gsum[tid] * (1.0f / (float)NN);
    __syncthreads();
    if (tid < LAT) {
        float mu = bmu[tid], lv = blv[tid];
#pragma unroll 4
        for (int k = 0; k < HID; k++) {
            float gk = gs[k];
            mu = fmaf(gk, Wmu[k * LAT + tid], mu);
            lv = fmaf(gk, Wlv[k * LAT + tid], lv);
        }
        out[(size_t)NN * CIN + tid] = mu;
        out[(size_t)NN * CIN + LAT + tid] = lv;
        zs[tid] = fmaf(eps[tid], expf(0.5f * lv), mu);
    }
    __syncthreads();
    float dv = bd1[tid];
#pragma unroll 4
    for (int k = 0; k < LAT; k++) dv = fmaf(zs[k], Wd1[k * HID + tid], dv);
    dv = fmaxf(dv, 0.f);
    // deterministic compaction of nonzero entries (ballot + popc prefix)
    unsigned m = __ballot_sync(0xffffffffu, dv > 0.f);
    if (lane == 0) wbase[wid] = __popc(m);
    __syncthreads();
    if (tid == 0) {
        int s = 0;
#pragma unroll
        for (int i = 0; i < 4; i++) { int t = wbase[i]; wbase[i] = s; s += t; }
        g_dcnt = s;
    }
    __syncthreads();
    if (dv > 0.f) {
        int p = wbase[wid] + __popc(m & ((1u << lane) - 1u));
        g_dnz[p] = make_int2(tid, __float_as_int(dv));
    }
}

// ---------------- decoder GEMV over NONZERO d rows only ---------------------
__global__ void __launch_bounds__(256) k_dec(const float* __restrict__ Wd2,
                                             const float* __restrict__ bd2,
                                             float* __restrict__ out) {
    __shared__ int2 sd[HID];
    __shared__ int  scnt;
    int tid = threadIdx.x;
    if (tid == 0) scnt = g_dcnt;
    if (tid < HID) sd[tid] = g_dnz[tid];
    __syncthreads();
    int cnt = scnt;
    int j = blockIdx.x * 256 + tid;              // float4 column index
    const int NC4 = NN * CIN / 4;                // 400000
    if (j >= NC4) return;
    const float4* W = (const float4*)Wd2;
    float4 acc = ((const float4*)bd2)[j];
#pragma unroll 4
    for (int t = 0; t < cnt; t++) {
        int2 e = sd[t];
        float dk = __int_as_float(e.y);
        float4 w = __ldcs(&W[(size_t)e.x * NC4 + j]);   // streaming, read-once
        fma4(acc, dk, w);
    }
    ((float4*)out)[j] = acc;
}

// ---------------- launch ----------------------------------------------------
extern "C" void kernel_launch(void* const* d_in, const int* in_sizes, int n_in,
                              void* d_out, int out_size) {
    const float* x   = (const float*)d_in[0];
    const int*   ei  = (const int*)  d_in[1];
    const float* eps = (const float*)d_in[2];
    const float* W1  = (const float*)d_in[3];
    const float* b1  = (const float*)d_in[4];
    const float* W2  = (const float*)d_in[5];
    const float* b2  = (const float*)d_in[6];
    const float* Wmu = (const float*)d_in[7];
    const float* bmu = (const float*)d_in[8];
    const float* Wlv = (const float*)d_in[9];
    const float* blv = (const float*)d_in[10];
    const float* Wd1 = (const float*)d_in[11];
    const float* bd1 = (const float*)d_in[12];
    const float* Wd2 = (const float*)d_in[13];
    const float* bd2 = (const float*)d_in[14];
    float* out = (float*)d_out;

    (void)in_sizes; (void)n_in; (void)out_size;

    const int EQ = EE / 4;
    k_init   <<<(NN * CIN / 2 + 255) / 256, 256>>>(x);
    k_deg    <<<(EQ + 255) / 256, 256>>>(ei + EE);
    k_scan   <<<1, 1024>>>();
    k_fill   <<<(EQ + 255) / 256, 256>>>(ei);
    k_g1l1   <<<NN / 8, 256>>>(W1, b1);          // fused gather1 + layer1
    k_gemm2  <<<(NN + 31) / 32, 256>>>(W2);
    k_gather2<<<NN / 8, 256>>>(b2);
    k_head   <<<1, 128>>>(eps, Wmu, bmu, Wlv, blv, Wd1, bd1, out);
    k_dec    <<<(NN * CIN / 4 + 255) / 256, 256>>>(Wd2, bd2, out);
}

// round 16
// speedup vs baseline: 1.6454x; 1.4059x over previous
#include <cuda_runtime.h>
#include <cuda_bf16.h>
#include <cuda_fp16.h>
#include <math.h>
#include <stdint.h>

#define NN   50000
#define EE   1600000
#define CIN  32
#define HID  128
#define LAT  64
#define HID4 (HID/4)
#define NPAD 53248                           // 1024 * 52 (scan tiling)

// ---------------- scratch (device globals; no allocations allowed) ----------
__device__ __align__(16) int g_ideg[NPAD];   // in-degree, zero-padded
__device__ __align__(16) int g_cnt[NN];      // fill cursors (init = rowptr)
__device__ __align__(16) int g_rowptr[NN + 4];
__device__ __align__(16) uint32_t g_coln[EE]; // {src:16 | half(nrm):16}
__device__ __align__(16) float g_dis[NN];
__device__ __align__(16) __nv_bfloat16 g_xh[NN * CIN];   // bf16 copy of x
__device__ __align__(16) uint2 g_h1h[NN * 32];           // h1 fp16 (4/uint2)
__device__ __half g_w2h[HID * HID];                      // W2 fp16 row-major
__device__ __align__(16) uint2 g_t2h[NN * 32];           // t2 fp16 (4/uint2)
__device__ __align__(16) float g_gsum[HID];
__device__ int  g_dcnt;
__device__ __align__(16) int2 g_dnz[HID];

// ---------------- helpers ---------------------------------------------------
__device__ __forceinline__ void fma4(float4& acc, float s, const float4& v) {
    acc.x = fmaf(s, v.x, acc.x);
    acc.y = fmaf(s, v.y, acc.y);
    acc.z = fmaf(s, v.z, acc.z);
    acc.w = fmaf(s, v.w, acc.w);
}
__device__ __forceinline__ __half2 h2b(uint32_t u) {
    return *reinterpret_cast<__half2*>(&u);
}
__device__ __forceinline__ uint32_t bh2(__half2 h) {
    return *reinterpret_cast<uint32_t*>(&h);
}
__device__ __forceinline__ void fma_h(float4& acc, float n, uint2 u) {
    float2 f0 = __half22float2(h2b(u.x));
    float2 f1 = __half22float2(h2b(u.y));
    acc.x = fmaf(n, f0.x, acc.x); acc.y = fmaf(n, f0.y, acc.y);
    acc.z = fmaf(n, f1.x, acc.z); acc.w = fmaf(n, f1.y, acc.w);
}
__device__ __forceinline__ void red_add_f4(float4* p, float4 v) {
    asm volatile("red.global.add.v4.f32 [%0], {%1,%2,%3,%4};"
                 :: "l"(p), "f"(v.x), "f"(v.y), "f"(v.z), "f"(v.w)
                 : "memory");
}
__device__ __forceinline__ uint32_t pack_sn(int s, float nrm) {
    return (uint32_t)s | ((uint32_t)__half_as_ushort(__float2half_rn(nrm)) << 16);
}
__device__ __forceinline__ int up_src(uint32_t c) { return (int)(c & 0xffffu); }
__device__ __forceinline__ float up_nrm(uint32_t c) {
    return __half2float(__ushort_as_half((unsigned short)(c >> 16)));
}

// ---------------- init: zero ideg (incl. pad) + gsum ------------------------
__global__ void k_init() {
    int i = blockIdx.x * 256 + threadIdx.x;
    if (i < NPAD) g_ideg[i] = 0;
    if (i < HID)  g_gsum[i] = 0.0f;
}

// ---------------- degree + x->bf16 + W2->fp16 (merged; deg is atomic-bound) -
__global__ void k_deg(const int* __restrict__ dst, const float* __restrict__ x,
                      const float* __restrict__ W2) {
    int t = blockIdx.x * 256 + threadIdx.x;          // 400128 threads
    int e0 = t * 4;
    if (e0 < EE) {
        int4 d4 = *(const int4*)(dst + e0);
        atomicAdd(&g_ideg[d4.x], 1);
        atomicAdd(&g_ideg[d4.y], 1);
        atomicAdd(&g_ideg[d4.z], 1);
        atomicAdd(&g_ideg[d4.w], 1);
    }
    for (int j = t; j < NN * CIN / 2; j += 400128) {
        float2 v = ((const float2*)x)[j];
        ((__nv_bfloat162*)g_xh)[j] = __float22bfloat162_rn(v);
    }
    if (t < HID * HID / 2) {
        float2 v = ((const float2*)W2)[t];
        ((__half2*)g_w2h)[t] = __float22half2_rn(v);
    }
}

// ---------------- single-block scan, int4 vectorized ------------------------
__global__ void __launch_bounds__(1024) k_scan() {
    const int G = 13;                          // 13 int4 = 52 elems / thread
    int tid = threadIdx.x;
    const int4* ideg4 = (const int4*)g_ideg;
    int local = 0;
#pragma unroll
    for (int g = 0; g < G; g++) {
        int4 v = ideg4[tid * G + g];           // pad reads are zeros
        local += v.x + v.y + v.z + v.w;
    }
    __shared__ int wsum[32];
    int lane = tid & 31, wid = tid >> 5;
    int inc = local;
#pragma unroll
    for (int off = 1; off < 32; off <<= 1) {
        int t = __shfl_up_sync(0xffffffffu, inc, off);
        if (lane >= off) inc += t;
    }
    if (lane == 31) wsum[wid] = inc;
    __syncthreads();
    if (wid == 0) {
        int v = wsum[lane];
#pragma unroll
        for (int off = 1; off < 32; off <<= 1) {
            int t = __shfl_up_sync(0xffffffffu, v, off);
            if (lane >= off) v += t;
        }
        wsum[lane] = v;
    }
    __syncthreads();
    int run = inc - local + (wid > 0 ? wsum[wid - 1] : 0);   // exclusive prefix
    int base = tid * 52;
#pragma unroll
    for (int g = 0; g < G; g++) {
        int4 d = ideg4[tid * G + g];           // reload (L1/L2 hit)
        int i0 = base + g * 4;
        int4 rp;
        float4 ds;
        rp.x = run;
        rp.y = rp.x + d.x;
        rp.z = rp.y + d.y;
        rp.w = rp.z + d.z;
        run  = rp.w + d.w;
        ds.x = rsqrtf((float)(d.x + 1));
        ds.y = rsqrtf((float)(d.y + 1));
        ds.z = rsqrtf((float)(d.z + 1));
        ds.w = rsqrtf((float)(d.w + 1));
        if (i0 + 3 < NN) {
            ((int4*)g_rowptr)[i0 >> 2] = rp;
            ((int4*)g_cnt)[i0 >> 2] = rp;
            ((float4*)g_dis)[i0 >> 2] = ds;
        } else {
            if (i0 + 0 < NN) { g_rowptr[i0+0] = rp.x; g_cnt[i0+0] = rp.x; g_dis[i0+0] = ds.x; }
            if (i0 + 1 < NN) { g_rowptr[i0+1] = rp.y; g_cnt[i0+1] = rp.y; g_dis[i0+1] = ds.y; }
            if (i0 + 2 < NN) { g_rowptr[i0+2] = rp.z; g_cnt[i0+2] = rp.z; g_dis[i0+2] = ds.z; }
            if (i0 + 3 < NN) { g_rowptr[i0+3] = rp.w; g_cnt[i0+3] = rp.w; g_dis[i0+3] = ds.w; }
        }
    }
    if (tid == 1023) g_rowptr[NN] = run;       // pads contribute 0
}

// ---------------- CSR fill: 4 edges/thread, packed 4B entries ---------------
__global__ void k_fill(const int* __restrict__ ei) {
    int e0 = (blockIdx.x * 256 + threadIdx.x) * 4;
    if (e0 >= EE) return;
    int4 s4 = *(const int4*)(ei + e0);
    int4 d4 = *(const int4*)(ei + EE + e0);
    float a0 = __ldg(&g_dis[s4.x]) * __ldg(&g_dis[d4.x]);
    float a1 = __ldg(&g_dis[s4.y]) * __ldg(&g_dis[d4.y]);
    float a2 = __ldg(&g_dis[s4.z]) * __ldg(&g_dis[d4.z]);
    float a3 = __ldg(&g_dis[s4.w]) * __ldg(&g_dis[d4.w]);
    int p0 = atomicAdd(&g_cnt[d4.x], 1);
    int p1 = atomicAdd(&g_cnt[d4.y], 1);
    int p2 = atomicAdd(&g_cnt[d4.z], 1);
    int p3 = atomicAdd(&g_cnt[d4.w], 1);
    g_coln[p0] = pack_sn(s4.x, a0);
    g_coln[p1] = pack_sn(s4.y, a1);
    g_coln[p2] = pack_sn(s4.z, a2);
    g_coln[p3] = pack_sn(s4.w, a3);
}

// ---------------- FUSED layer-1: gather (warp/node) + matmul + relu ---------
__global__ void __launch_bounds__(256) k_g1l1(const float* __restrict__ W1,
                                              const float* __restrict__ b1) {
    __shared__ float sW[CIN * HID];   // 16 KB
    __shared__ float sv[8 * CIN];
    int tid = threadIdx.x;
    int r = tid >> 5, lane = tid & 31;
    int w = blockIdx.x * 8 + r;                  // NN % 8 == 0
    for (int i = tid; i < CIN * HID; i += 256) sW[i] = W1[i];
    float di = g_dis[w];
    int e   = g_rowptr[w];
    int end = g_rowptr[w + 1];
    float acc = __bfloat162float(g_xh[w * CIN + lane]) * di * di;
    int e4 = e + ((end - e) & ~3);
    for (; e < e4; e += 4) {
        uint32_t c0 = __ldg(&g_coln[e]);
        uint32_t c1 = __ldg(&g_coln[e + 1]);
        uint32_t c2 = __ldg(&g_coln[e + 2]);
        uint32_t c3 = __ldg(&g_coln[e + 3]);
        float v0 = __bfloat162float(g_xh[up_src(c0) * CIN + lane]);
        float v1 = __bfloat162float(g_xh[up_src(c1) * CIN + lane]);
        float v2 = __bfloat162float(g_xh[up_src(c2) * CIN + lane]);
        float v3 = __bfloat162float(g_xh[up_src(c3) * CIN + lane]);
        acc = fmaf(v0, up_nrm(c0), acc);
        acc = fmaf(v1, up_nrm(c1), acc);
        acc = fmaf(v2, up_nrm(c2), acc);
        acc = fmaf(v3, up_nrm(c3), acc);
    }
    for (; e < end; e++) {
        uint32_t c = __ldg(&g_coln[e]);
        acc = fmaf(__bfloat162float(g_xh[up_src(c) * CIN + lane]), up_nrm(c), acc);
    }
    sv[tid] = acc;
    __syncthreads();
    float4 a4 = ((const float4*)b1)[lane];
    const float4* sW4 = (const float4*)sW;
#pragma unroll
    for (int k = 0; k < CIN; k++) {
        fma4(a4, sv[r * CIN + k], sW4[k * HID4 + lane]);
    }
    a4.x = fmaxf(a4.x, 0.f); a4.y = fmaxf(a4.y, 0.f);
    a4.z = fmaxf(a4.z, 0.f); a4.w = fmaxf(a4.w, 0.f);
    uint2 o;
    o.x = bh2(__float22half2_rn(make_float2(a4.x, a4.y)));
    o.y = bh2(__float22half2_rn(make_float2(a4.z, a4.w)));
    g_h1h[w * 32 + lane] = o;
}

// ---------------- GEMM2: t2(fp16) = h1(fp16) @ W2(fp16), HFMA2 -------------
// half2 accumulation over 16-k chunks, flushed to fp32.
__global__ void __launch_bounds__(256) k_gemm2() {
    int tid = threadIdx.x;
    int cg = tid & 31, rl = tid >> 5;
    int rbase = blockIdx.x * 32 + rl;
    int r0 = rbase, r1 = rbase + 8, r2 = rbase + 16, r3 = rbase + 24;
    bool v0 = r0 < NN, v1 = r1 < NN, v2 = r2 < NN, v3 = r3 < NN;
    const uint2* A = g_h1h;
    const uint2* W = (const uint2*)g_w2h;        // [k][n/4] (4 halfs per uint2)
    float4 f0 = make_float4(0.f,0.f,0.f,0.f), f1 = f0, f2 = f0, f3 = f0;
    uint2 zu = make_uint2(0u, 0u);
    __half2 hz = __float2half2_rn(0.f);
#pragma unroll
    for (int c = 0; c < 8; c++) {                // 8 chunks of 16 k
        __half2 h00 = hz, h01 = hz, h10 = hz, h11 = hz;
        __half2 h20 = hz, h21 = hz, h30 = hz, h31 = hz;
#pragma unroll
        for (int q = 0; q < 4; q++) {
            int kq = c * 4 + q;                  // k-quad: k = kq*4 .. +3
            uint2 a0 = v0 ? __ldg(&A[r0 * 32 + kq]) : zu;
            uint2 a1 = v1 ? __ldg(&A[r1 * 32 + kq]) : zu;
            uint2 a2 = v2 ? __ldg(&A[r2 * 32 + kq]) : zu;
            uint2 a3 = v3 ? __ldg(&A[r3 * 32 + kq]) : zu;
            uint2 w0u = __ldg(&W[(kq * 4 + 0) * 32 + cg]);
            uint2 w1u = __ldg(&W[(kq * 4 + 1) * 32 + cg]);
            uint2 w2u = __ldg(&W[(kq * 4 + 2) * 32 + cg]);
            uint2 w3u = __ldg(&W[(kq * 4 + 3) * 32 + cg]);
            __half2 w0l = h2b(w0u.x), w0h = h2b(w0u.y);
            __half2 w1l = h2b(w1u.x), w1h = h2b(w1u.y);
            __half2 w2l = h2b(w2u.x), w2h = h2b(w2u.y);
            __half2 w3l = h2b(w3u.x), w3h = h2b(w3u.y);
            __half2 p, b;
#define ROW(a, hA, hB) \
            p = h2b(a.x); \
            b = __low2half2(p);  hA = __hfma2(b, w0l, hA); hB = __hfma2(b, w0h, hB); \
            b = __high2half2(p); hA = __hfma2(b, w1l, hA); hB = __hfma2(b, w1h, hB); \
            p = h2b(a.y); \
            b = __low2half2(p);  hA = __hfma2(b, w2l, hA); hB = __hfma2(b, w2h, hB); \
            b = __high2half2(p); hA = __hfma2(b, w3l, hA); hB = __hfma2(b, w3h, hB);
            ROW(a0, h00, h01)
            ROW(a1, h10, h11)
            ROW(a2, h20, h21)
            ROW(a3, h30, h31)
#undef ROW
        }
        float2 t;
        t = __half22float2(h00); f0.x += t.x; f0.y += t.y;
        t = __half22float2(h01); f0.z += t.x; f0.w += t.y;
        t = __half22float2(h10); f1.x += t.x; f1.y += t.y;
        t = __half22float2(h11); f1.z += t.x; f1.w += t.y;
        t = __half22float2(h20); f2.x += t.x; f2.y += t.y;
        t = __half22float2(h21); f2.z += t.x; f2.w += t.y;
        t = __half22float2(h30); f3.x += t.x; f3.y += t.y;
        t = __half22float2(h31); f3.z += t.x; f3.w += t.y;
    }
    uint2 o;
    if (v0) {
        o.x = bh2(__float22half2_rn(make_float2(f0.x, f0.y)));
        o.y = bh2(__float22half2_rn(make_float2(f0.z, f0.w)));
        g_t2h[r0 * 32 + cg] = o;
    }
    if (v1) {
        o.x = bh2(__float22half2_rn(make_float2(f1.x, f1.y)));
        o.y = bh2(__float22half2_rn(make_float2(f1.z, f1.w)));
        g_t2h[r1 * 32 + cg] = o;
    }
    if (v2) {
        o.x = bh2(__float22half2_rn(make_float2(f2.x, f2.y)));
        o.y = bh2(__float22half2_rn(make_float2(f2.z, f2.w)));
        g_t2h[r2 * 32 + cg] = o;
    }
    if (v3) {
        o.x = bh2(__float22half2_rn(make_float2(f3.x, f3.y)));
        o.y = bh2(__float22half2_rn(make_float2(f3.z, f3.w)));
        g_t2h[r3 * 32 + cg] = o;
    }
}

// ---------------- layer-2 gather + bias + relu + fused mean -> gsum ---------
__global__ void __launch_bounds__(256) k_gather2(const float* __restrict__ b2) {
    __shared__ float sacc[2 * HID];
    int tid = threadIdx.x;
    int w = blockIdx.x * 8 + (tid >> 5);
    int lane = tid & 31;
    float di = g_dis[w];
    int e   = g_rowptr[w];
    int end = g_rowptr[w + 1];
    const uint2* T2 = g_t2h;
    float sc = di * di;
    float4 acc = make_float4(0.f, 0.f, 0.f, 0.f);
    fma_h(acc, sc, T2[w * 32 + lane]);
    int e4 = e + ((end - e) & ~3);
    for (; e < e4; e += 4) {
        uint32_t c0 = __ldg(&g_coln[e]);
        uint32_t c1 = __ldg(&g_coln[e + 1]);
        uint32_t c2 = __ldg(&g_coln[e + 2]);
        uint32_t c3 = __ldg(&g_coln[e + 3]);
        uint2 u0 = __ldg(&T2[up_src(c0) * 32 + lane]);
        uint2 u1 = __ldg(&T2[up_src(c1) * 32 + lane]);
        uint2 u2 = __ldg(&T2[up_src(c2) * 32 + lane]);
        uint2 u3 = __ldg(&T2[up_src(c3) * 32 + lane]);
        fma_h(acc, up_nrm(c0), u0);
        fma_h(acc, up_nrm(c1), u1);
        fma_h(acc, up_nrm(c2), u2);
        fma_h(acc, up_nrm(c3), u3);
    }
    for (; e < end; e++) {
        uint32_t c = __ldg(&g_coln[e]);
        fma_h(acc, up_nrm(c), __ldg(&T2[up_src(c) * 32 + lane]));
    }
    float4 b = ((const float4*)b2)[lane];
    acc.x = fmaxf(acc.x + b.x, 0.f); acc.y = fmaxf(acc.y + b.y, 0.f);
    acc.z = fmaxf(acc.z + b.z, 0.f); acc.w = fmaxf(acc.w + b.w, 0.f);
    int half_ = tid >> 7;
    int wi    = (tid >> 5) & 3;
    float4* s4 = (float4*)sacc;
    if (wi == 0) s4[half_ * 32 + lane] = acc;
    __syncthreads();
    if (wi == 1) fma4(s4[half_ * 32 + lane], 1.f, acc);
    __syncthreads();
    if (wi == 2) fma4(s4[half_ * 32 + lane], 1.f, acc);
    __syncthreads();
    if (wi == 3) fma4(s4[half_ * 32 + lane], 1.f, acc);
    __syncthreads();
    if (tid < 32) {
        float4 v0 = s4[tid];
        float4 v1 = s4[32 + tid];
        v0.x += v1.x; v0.y += v1.y; v0.z += v1.z; v0.w += v1.w;
        red_add_f4(&((float4*)g_gsum)[tid], v0);
    }
}

// ---------------- head: mu, logvar (to out), z, d -> compacted nonzeros -----
__global__ void __launch_bounds__(128) k_head(const float* __restrict__ eps,
                                              const float* __restrict__ Wmu, const float* __restrict__ bmu,
                                              const float* __restrict__ Wlv, const float* __restrict__ blv,
                                              const float* __restrict__ Wd1, const float* __restrict__ bd1,
                                              float* __restrict__ out) {
    __shared__ float gs[HID], zs[LAT];
    __shared__ int wbase[4];
    int tid = threadIdx.x;
    int lane = tid & 31, wid = tid >> 5;
    gs[tid] = g_gsum[tid] * (1.0f / (float)NN);
    __syncthreads();
    if (tid < LAT) {
        float mu = bmu[tid], lv = blv[tid];
#pragma unroll 4
        for (int k = 0; k < HID; k++) {
            float gk = gs[k];
            mu = fmaf(gk, Wmu[k * LAT + tid], mu);
            lv = fmaf(gk, Wlv[k * LAT + tid], lv);
        }
        out[(size_t)NN * CIN + tid] = mu;
        out[(size_t)NN * CIN + LAT + tid] = lv;
        zs[tid] = fmaf(eps[tid], expf(0.5f * lv), mu);
    }
    __syncthreads();
    float dv = bd1[tid];
#pragma unroll 4
    for (int k = 0; k < LAT; k++) dv = fmaf(zs[k], Wd1[k * HID + tid], dv);
    dv = fmaxf(dv, 0.f);
    unsigned m = __ballot_sync(0xffffffffu, dv > 0.f);
    if (lane == 0) wbase[wid] = __popc(m);
    __syncthreads();
    if (tid == 0) {
        int s = 0;
#pragma unroll
        for (int i = 0; i < 4; i++) { int t = wbase[i]; wbase[i] = s; s += t; }
        g_dcnt = s;
    }
    __syncthreads();
    if (dv > 0.f) {
        int p = wbase[wid] + __popc(m & ((1u << lane) - 1u));
        g_dnz[p] = make_int2(tid, __float_as_int(dv));
    }
}

// ---------------- decoder GEMV over NONZERO d rows only ---------------------
__global__ void __launch_bounds__(256) k_dec(const float* __restrict__ Wd2,
                                             const float* __restrict__ bd2,
                                             float* __restrict__ out) {
    __shared__ int2 sd[HID];
    __shared__ int  scnt;
    int tid = threadIdx.x;
    if (tid == 0) scnt = g_dcnt;
    if (tid < HID) sd[tid] = g_dnz[tid];
    __syncthreads();
    int cnt = scnt;
    int j = blockIdx.x * 256 + tid;
    const int NC4 = NN * CIN / 4;
    if (j >= NC4) return;
    const float4* W = (const float4*)Wd2;
    float4 acc = ((const float4*)bd2)[j];
#pragma unroll 4
    for (int t = 0; t < cnt; t++) {
        int2 e = sd[t];
        float dk = __int_as_float(e.y);
        float4 w = __ldcs(&W[(size_t)e.x * NC4 + j]);
        fma4(acc, dk, w);
    }
    ((float4*)out)[j] = acc;
}

// ---------------- launch ----------------------------------------------------
extern "C" void kernel_launch(void* const* d_in, const int* in_sizes, int n_in,
                              void* d_out, int out_size) {
    const float* x   = (const float*)d_in[0];
    const int*   ei  = (const int*)  d_in[1];
    const float* eps = (const float*)d_in[2];
    const float* W1  = (const float*)d_in[3];
    const float* b1  = (const float*)d_in[4];
    const float* W2  = (const float*)d_in[5];
    const float* b2  = (const float*)d_in[6];
    const float* Wmu = (const float*)d_in[7];
    const float* bmu = (const float*)d_in[8];
    const float* Wlv = (const float*)d_in[9];
    const float* blv = (const float*)d_in[10];
    const float* Wd1 = (const float*)d_in[11];
    const float* bd1 = (const float*)d_in[12];
    const float* Wd2 = (const float*)d_in[13];
    const float* bd2 = (const float*)d_in[14];
    float* out = (float*)d_out;

    (void)in_sizes; (void)n_in; (void)out_size;

    const int EQ = EE / 4;                      // 400000 quads
    k_init   <<<NPAD / 256, 256>>>();
    k_deg    <<<(EQ + 255) / 256, 256>>>(ei + EE, x, W2);   // + conversions
    k_scan   <<<1, 1024>>>();
    k_fill   <<<(EQ + 255) / 256, 256>>>(ei);
    k_g1l1   <<<NN / 8, 256>>>(W1, b1);
    k_gemm2  <<<(NN + 31) / 32, 256>>>();
    k_gather2<<<NN / 8, 256>>>(b2);
    k_head   <<<1, 128>>>(eps, Wmu, bmu, Wlv, blv, Wd1, bd1, out);
    k_dec    <<<(NN * CIN / 4 + 255) / 256, 256>>>(Wd2, bd2, out);
}

// round 17
// speedup vs baseline: 1.6687x; 1.0142x over previous
#include <cuda_runtime.h>
#include <cuda_bf16.h>
#include <cuda_fp16.h>
#include <math.h>
#include <stdint.h>

#define NN   50000
#define EE   1600000
#define CIN  32
#define HID  128
#define LAT  64
#define HID4 (HID/4)
#define CAP  128                             // max in-degree capacity (>=12 sigma)

// ---------------- scratch (device globals; no allocations allowed) ----------
__device__ __align__(16) int g_cnt[NN];                  // bucket counts
__device__ __align__(16) int g_bkt[NN * CAP];            // src indices, padded
__device__ __align__(16) float g_dis[NN];
__device__ __align__(16) __nv_bfloat16 g_xh[NN * CIN];   // bf16 copy of x
__device__ __align__(16) uint2 g_h1h[NN * 32];           // h1 fp16 (4/uint2)
__device__ __half g_w2h[HID * HID];                      // W2 fp16 row-major
__device__ __align__(16) uint2 g_t2h[NN * 32];           // t2 fp16 (4/uint2)
__device__ __align__(16) float g_gsum[HID];
__device__ int  g_dcnt;
__device__ __align__(16) int2 g_dnz[HID];

// ---------------- helpers ---------------------------------------------------
__device__ __forceinline__ void fma4(float4& acc, float s, const float4& v) {
    acc.x = fmaf(s, v.x, acc.x);
    acc.y = fmaf(s, v.y, acc.y);
    acc.z = fmaf(s, v.z, acc.z);
    acc.w = fmaf(s, v.w, acc.w);
}
__device__ __forceinline__ __half2 h2b(uint32_t u) {
    return *reinterpret_cast<__half2*>(&u);
}
__device__ __forceinline__ uint32_t bh2(__half2 h) {
    return *reinterpret_cast<uint32_t*>(&h);
}
__device__ __forceinline__ void fma_h(float4& acc, float n, uint2 u) {
    float2 f0 = __half22float2(h2b(u.x));
    float2 f1 = __half22float2(h2b(u.y));
    acc.x = fmaf(n, f0.x, acc.x); acc.y = fmaf(n, f0.y, acc.y);
    acc.z = fmaf(n, f1.x, acc.z); acc.w = fmaf(n, f1.y, acc.w);
}
__device__ __forceinline__ void red_add_f4(float4* p, float4 v) {
    asm volatile("red.global.add.v4.f32 [%0], {%1,%2,%3,%4};"
                 :: "l"(p), "f"(v.x), "f"(v.y), "f"(v.z), "f"(v.w)
                 : "memory");
}

// ---------------- init: zero cnt + gsum -------------------------------------
__global__ void k_init() {
    int i = blockIdx.x * 256 + threadIdx.x;
    if (i < NN)  g_cnt[i] = 0;
    if (i < HID) g_gsum[i] = 0.0f;
}

// ---------------- merged degree+fill: 4 edges/thread into padded buckets ----
__global__ void k_degfill(const int* __restrict__ ei) {
    int e0 = (blockIdx.x * 256 + threadIdx.x) * 4;
    if (e0 >= EE) return;                      // EE % 4 == 0
    int4 s4 = *(const int4*)(ei + e0);
    int4 d4 = *(const int4*)(ei + EE + e0);
    int p0 = atomicAdd(&g_cnt[d4.x], 1);
    int p1 = atomicAdd(&g_cnt[d4.y], 1);
    int p2 = atomicAdd(&g_cnt[d4.z], 1);
    int p3 = atomicAdd(&g_cnt[d4.w], 1);
    g_bkt[d4.x * CAP + p0] = s4.x;
    g_bkt[d4.y * CAP + p1] = s4.y;
    g_bkt[d4.z * CAP + p2] = s4.z;
    g_bkt[d4.w * CAP + p3] = s4.w;
}

// ---------------- dis + x->bf16 + W2->fp16 ----------------------------------
__global__ void k_dis(const float* __restrict__ x, const float* __restrict__ W2) {
    int t = blockIdx.x * 256 + threadIdx.x;          // 800000 threads
    if (t < NN) g_dis[t] = rsqrtf((float)(g_cnt[t] + 1));
    if (t < NN * CIN / 2) {
        float2 v = ((const float2*)x)[t];
        ((__nv_bfloat162*)g_xh)[t] = __float22bfloat162_rn(v);
    }
    if (t < HID * HID / 2) {
        float2 v = ((const float2*)W2)[t];
        ((__half2*)g_w2h)[t] = __float22half2_rn(v);
    }
}

// ---------------- FUSED layer-1: gather (warp/node) + matmul + relu ---------
__global__ void __launch_bounds__(256) k_g1l1(const float* __restrict__ W1,
                                              const float* __restrict__ b1) {
    __shared__ float sW[CIN * HID];   // 16 KB
    __shared__ float sv[8 * CIN];
    int tid = threadIdx.x;
    int r = tid >> 5, lane = tid & 31;
    int w = blockIdx.x * 8 + r;                  // NN % 8 == 0
    for (int i = tid; i < CIN * HID; i += 256) sW[i] = W1[i];
    float di = g_dis[w];
    int cnt = g_cnt[w];
    const int* bkt = g_bkt + w * CAP;
    float acc = __bfloat162float(g_xh[w * CIN + lane]) * di * di;
    int e = 0, e4 = cnt & ~3;
    for (; e < e4; e += 4) {
        int s0 = __ldg(&bkt[e]);
        int s1 = __ldg(&bkt[e + 1]);
        int s2 = __ldg(&bkt[e + 2]);
        int s3 = __ldg(&bkt[e + 3]);
        float n0 = __ldg(&g_dis[s0]) * di;
        float n1 = __ldg(&g_dis[s1]) * di;
        float n2 = __ldg(&g_dis[s2]) * di;
        float n3 = __ldg(&g_dis[s3]) * di;
        float v0 = __bfloat162float(g_xh[s0 * CIN + lane]);
        float v1 = __bfloat162float(g_xh[s1 * CIN + lane]);
        float v2 = __bfloat162float(g_xh[s2 * CIN + lane]);
        float v3 = __bfloat162float(g_xh[s3 * CIN + lane]);
        acc = fmaf(v0, n0, acc);
        acc = fmaf(v1, n1, acc);
        acc = fmaf(v2, n2, acc);
        acc = fmaf(v3, n3, acc);
    }
    for (; e < cnt; e++) {
        int s = __ldg(&bkt[e]);
        acc = fmaf(__bfloat162float(g_xh[s * CIN + lane]),
                   __ldg(&g_dis[s]) * di, acc);
    }
    sv[tid] = acc;
    __syncthreads();
    float4 a4 = ((const float4*)b1)[lane];
    const float4* sW4 = (const float4*)sW;
#pragma unroll
    for (int k = 0; k < CIN; k++) {
        fma4(a4, sv[r * CIN + k], sW4[k * HID4 + lane]);
    }
    a4.x = fmaxf(a4.x, 0.f); a4.y = fmaxf(a4.y, 0.f);
    a4.z = fmaxf(a4.z, 0.f); a4.w = fmaxf(a4.w, 0.f);
    uint2 o;
    o.x = bh2(__float22half2_rn(make_float2(a4.x, a4.y)));
    o.y = bh2(__float22half2_rn(make_float2(a4.z, a4.w)));
    g_h1h[w * 32 + lane] = o;
}

// ---------------- GEMM2: t2(fp16) = h1(fp16) @ W2(fp16), HFMA2 -------------
__global__ void __launch_bounds__(256) k_gemm2() {
    int tid = threadIdx.x;
    int cg = tid & 31, rl = tid >> 5;
    int rbase = blockIdx.x * 32 + rl;
    int r0 = rbase, r1 = rbase + 8, r2 = rbase + 16, r3 = rbase + 24;
    bool v0 = r0 < NN, v1 = r1 < NN, v2 = r2 < NN, v3 = r3 < NN;
    const uint2* A = g_h1h;
    const uint2* W = (const uint2*)g_w2h;        // [k][n/4]
    float4 f0 = make_float4(0.f,0.f,0.f,0.f), f1 = f0, f2 = f0, f3 = f0;
    uint2 zu = make_uint2(0u, 0u);
    __half2 hz = __float2half2_rn(0.f);
#pragma unroll
    for (int c = 0; c < 8; c++) {                // 8 chunks of 16 k
        __half2 h00 = hz, h01 = hz, h10 = hz, h11 = hz;
        __half2 h20 = hz, h21 = hz, h30 = hz, h31 = hz;
#pragma unroll
        for (int q = 0; q < 4; q++) {
            int kq = c * 4 + q;
            uint2 a0 = v0 ? __ldg(&A[r0 * 32 + kq]) : zu;
            uint2 a1 = v1 ? __ldg(&A[r1 * 32 + kq]) : zu;
            uint2 a2 = v2 ? __ldg(&A[r2 * 32 + kq]) : zu;
            uint2 a3 = v3 ? __ldg(&A[r3 * 32 + kq]) : zu;
            uint2 w0u = __ldg(&W[(kq * 4 + 0) * 32 + cg]);
            uint2 w1u = __ldg(&W[(kq * 4 + 1) * 32 + cg]);
            uint2 w2u = __ldg(&W[(kq * 4 + 2) * 32 + cg]);
            uint2 w3u = __ldg(&W[(kq * 4 + 3) * 32 + cg]);
            __half2 w0l = h2b(w0u.x), w0h = h2b(w0u.y);
            __half2 w1l = h2b(w1u.x), w1h = h2b(w1u.y);
            __half2 w2l = h2b(w2u.x), w2h = h2b(w2u.y);
            __half2 w3l = h2b(w3u.x), w3h = h2b(w3u.y);
            __half2 p, b;
#define ROW(a, hA, hB) \
            p = h2b(a.x); \
            b = __low2half2(p);  hA = __hfma2(b, w0l, hA); hB = __hfma2(b, w0h, hB); \
            b = __high2half2(p); hA = __hfma2(b, w1l, hA); hB = __hfma2(b, w1h, hB); \
            p = h2b(a.y); \
            b = __low2half2(p);  hA = __hfma2(b, w2l, hA); hB = __hfma2(b, w2h, hB); \
            b = __high2half2(p); hA = __hfma2(b, w3l, hA); hB = __hfma2(b, w3h, hB);
            ROW(a0, h00, h01)
            ROW(a1, h10, h11)
            ROW(a2, h20, h21)
            ROW(a3, h30, h31)
#undef ROW
        }
        float2 t;
        t = __half22float2(h00); f0.x += t.x; f0.y += t.y;
        t = __half22float2(h01); f0.z += t.x; f0.w += t.y;
        t = __half22float2(h10); f1.x += t.x; f1.y += t.y;
        t = __half22float2(h11); f1.z += t.x; f1.w += t.y;
        t = __half22float2(h20); f2.x += t.x; f2.y += t.y;
        t = __half22float2(h21); f2.z += t.x; f2.w += t.y;
        t = __half22float2(h30); f3.x += t.x; f3.y += t.y;
        t = __half22float2(h31); f3.z += t.x; f3.w += t.y;
    }
    uint2 o;
    if (v0) {
        o.x = bh2(__float22half2_rn(make_float2(f0.x, f0.y)));
        o.y = bh2(__float22half2_rn(make_float2(f0.z, f0.w)));
        g_t2h[r0 * 32 + cg] = o;
    }
    if (v1) {
        o.x = bh2(__float22half2_rn(make_float2(f1.x, f1.y)));
        o.y = bh2(__float22half2_rn(make_float2(f1.z, f1.w)));
        g_t2h[r1 * 32 + cg] = o;
    }
    if (v2) {
        o.x = bh2(__float22half2_rn(make_float2(f2.x, f2.y)));
        o.y = bh2(__float22half2_rn(make_float2(f2.z, f2.w)));
        g_t2h[r2 * 32 + cg] = o;
    }
    if (v3) {
        o.x = bh2(__float22half2_rn(make_float2(f3.x, f3.y)));
        o.y = bh2(__float22half2_rn(make_float2(f3.z, f3.w)));
        g_t2h[r3 * 32 + cg] = o;
    }
}

// ---------------- layer-2 gather + bias + relu + fused mean -> gsum ---------
__global__ void __launch_bounds__(256) k_gather2(const float* __restrict__ b2) {
    __shared__ float sacc[2 * HID];
    int tid = threadIdx.x;
    int w = blockIdx.x * 8 + (tid >> 5);
    int lane = tid & 31;
    float di = g_dis[w];
    int cnt = g_cnt[w];
    const int* bkt = g_bkt + w * CAP;
    const uint2* T2 = g_t2h;
    float sc = di * di;
    float4 acc = make_float4(0.f, 0.f, 0.f, 0.f);
    fma_h(acc, sc, T2[w * 32 + lane]);
    int e = 0, e4 = cnt & ~3;
    for (; e < e4; e += 4) {
        int s0 = __ldg(&bkt[e]);
        int s1 = __ldg(&bkt[e + 1]);
        int s2 = __ldg(&bkt[e + 2]);
        int s3 = __ldg(&bkt[e + 3]);
        float n0 = __ldg(&g_dis[s0]) * di;
        float n1 = __ldg(&g_dis[s1]) * di;
        float n2 = __ldg(&g_dis[s2]) * di;
        float n3 = __ldg(&g_dis[s3]) * di;
        uint2 u0 = __ldg(&T2[s0 * 32 + lane]);
        uint2 u1 = __ldg(&T2[s1 * 32 + lane]);
        uint2 u2 = __ldg(&T2[s2 * 32 + lane]);
        uint2 u3 = __ldg(&T2[s3 * 32 + lane]);
        fma_h(acc, n0, u0);
        fma_h(acc, n1, u1);
        fma_h(acc, n2, u2);
        fma_h(acc, n3, u3);
    }
    for (; e < cnt; e++) {
        int s = __ldg(&bkt[e]);
        fma_h(acc, __ldg(&g_dis[s]) * di, __ldg(&T2[s * 32 + lane]));
    }
    float4 b = ((const float4*)b2)[lane];
    acc.x = fmaxf(acc.x + b.x, 0.f); acc.y = fmaxf(acc.y + b.y, 0.f);
    acc.z = fmaxf(acc.z + b.z, 0.f); acc.w = fmaxf(acc.w + b.w, 0.f);
    int half_ = tid >> 7;
    int wi    = (tid >> 5) & 3;
    float4* s4 = (float4*)sacc;
    if (wi == 0) s4[half_ * 32 + lane] = acc;
    __syncthreads();
    if (wi == 1) fma4(s4[half_ * 32 + lane], 1.f, acc);
    __syncthreads();
    if (wi == 2) fma4(s4[half_ * 32 + lane], 1.f, acc);
    __syncthreads();
    if (wi == 3) fma4(s4[half_ * 32 + lane], 1.f, acc);
    __syncthreads();
    if (tid < 32) {
        float4 v0 = s4[tid];
        float4 v1 = s4[32 + tid];
        v0.x += v1.x; v0.y += v1.y; v0.z += v1.z; v0.w += v1.w;
        red_add_f4(&((float4*)g_gsum)[tid], v0);
    }
}

// ---------------- head: mu, logvar (to out), z, d -> compacted nonzeros -----
__global__ void __launch_bounds__(128) k_head(const float* __restrict__ eps,
                                              const float* __restrict__ Wmu, const float* __restrict__ bmu,
                                              const float* __restrict__ Wlv, const float* __restrict__ blv,
                                              const float* __restrict__ Wd1, const float* __restrict__ bd1,
                                              float* __restrict__ out) {
    __shared__ float gs[HID], zs[LAT];
    __shared__ int wbase[4];
    int tid = threadIdx.x;
    int lane = tid & 31, wid = tid >> 5;
    gs[tid] = g_gsum[tid] * (1.0f / (float)NN);
    __syncthreads();
    if (tid < LAT) {
        float mu = bmu[tid], lv = blv[tid];
#pragma unroll 4
        for (int k = 0; k < HID; k++) {
            float gk = gs[k];
            mu = fmaf(gk, Wmu[k * LAT + tid], mu);
            lv = fmaf(gk, Wlv[k * LAT + tid], lv);
        }
        out[(size_t)NN * CIN + tid] = mu;
        out[(size_t)NN * CIN + LAT + tid] = lv;
        zs[tid] = fmaf(eps[tid], expf(0.5f * lv), mu);
    }
    __syncthreads();
    float dv = bd1[tid];
#pragma unroll 4
    for (int k = 0; k < LAT; k++) dv = fmaf(zs[k], Wd1[k * HID + tid], dv);
    dv = fmaxf(dv, 0.f);
    unsigned m = __ballot_sync(0xffffffffu, dv > 0.f);
    if (lane == 0) wbase[wid] = __popc(m);
    __syncthreads();
    if (tid == 0) {
        int s = 0;
#pragma unroll
        for (int i = 0; i < 4; i++) { int t = wbase[i]; wbase[i] = s; s += t; }
        g_dcnt = s;
    }
    __syncthreads();
    if (dv > 0.f) {
        int p = wbase[wid] + __popc(m & ((1u << lane) - 1u));
        g_dnz[p] = make_int2(tid, __float_as_int(dv));
    }
}

// ---------------- decoder GEMV over NONZERO d rows only ---------------------
__global__ void __launch_bounds__(256) k_dec(const float* __restrict__ Wd2,
                                             const float* __restrict__ bd2,
                                             float* __restrict__ out) {
    __shared__ int2 sd[HID];
    __shared__ int  scnt;
    int tid = threadIdx.x;
    if (tid == 0) scnt = g_dcnt;
    if (tid < HID) sd[tid] = g_dnz[tid];
    __syncthreads();
    int cnt = scnt;
    int j = blockIdx.x * 256 + tid;
    const int NC4 = NN * CIN / 4;
    if (j >= NC4) return;
    const float4* W = (const float4*)Wd2;
    float4 acc = ((const float4*)bd2)[j];
#pragma unroll 4
    for (int t = 0; t < cnt; t++) {
        int2 e = sd[t];
        float dk = __int_as_float(e.y);
        float4 w = __ldcs(&W[(size_t)e.x * NC4 + j]);
        fma4(acc, dk, w);
    }
    ((float4*)out)[j] = acc;
}

// ---------------- launch ----------------------------------------------------
extern "C" void kernel_launch(void* const* d_in, const int* in_sizes, int n_in,
                              void* d_out, int out_size) {
    const float* x   = (const float*)d_in[0];
    const int*   ei  = (const int*)  d_in[1];
    const float* eps = (const float*)d_in[2];
    const float* W1  = (const float*)d_in[3];
    const float* b1  = (const float*)d_in[4];
    const float* W2  = (const float*)d_in[5];
    const float* b2  = (const float*)d_in[6];
    const float* Wmu = (const float*)d_in[7];
    const float* bmu = (const float*)d_in[8];
    const float* Wlv = (const float*)d_in[9];
    const float* blv = (const float*)d_in[10];
    const float* Wd1 = (const float*)d_in[11];
    const float* bd1 = (const float*)d_in[12];
    const float* Wd2 = (const float*)d_in[13];
    const float* bd2 = (const float*)d_in[14];
    float* out = (float*)d_out;

    (void)in_sizes; (void)n_in; (void)out_size;

    const int EQ = EE / 4;                      // 400000 quads
    k_init   <<<(NN + 255) / 256, 256>>>();
    k_degfill<<<(EQ + 255) / 256, 256>>>(ei);
    k_dis    <<<(NN * CIN / 2 + 255) / 256, 256>>>(x, W2);
    k_g1l1   <<<NN / 8, 256>>>(W1, b1);
    k_gemm2  <<<(NN + 31) / 32, 256>>>();
    k_gather2<<<NN / 8, 256>>>(b2);
    k_head   <<<1, 128>>>(eps, Wmu, bmu, Wlv, blv, Wd1, bd1, out);
    k_dec    <<<(NN * CIN / 4 + 255) / 256, 256>>>(Wd2, bd2, out);
}